// round 1
// baseline (speedup 1.0000x reference)
#include <cuda_runtime.h>
#include <math.h>

// Problem constants (shapes fixed by the dataset; N/P/B re-derived from sizes)
#define Dd 256
#define Hh 8
#define DHh 32
#define Pmax 128
#define Bmax 16
#define Nmax 6000
#define FF 1024

// ---------------- scratch (static __device__ — no allocation allowed) ----------
__device__ float d_q[Nmax * Dd];
__device__ float d_k[Pmax * Dd];
__device__ float d_v[Pmax * Dd];
__device__ float d_scores[(size_t)Nmax * Hh * Pmax];
__device__ float d_ctx[(size_t)Bmax * Nmax * Dd];     // ctx, later reused as y
__device__ float d_tmp[(size_t)Bmax * Nmax * Dd];     // attn_out
__device__ float d_x[(size_t)Bmax * Nmax * Dd];       // post-LN1 activations
__device__ float d_hidden[(size_t)Bmax * Nmax * FF];  // FFN hidden
__device__ int   d_segs[2 * Bmax];
__device__ int   d_hasany[Bmax];

// ---------------- segment scan (batch_assignment is sorted) --------------------
__global__ void seg_kernel(const int* __restrict__ ba, int P, int B) {
    if (threadIdx.x != 0 || blockIdx.x != 0) return;
    for (int b = 0; b < B; b++) {
        int s = P, e = 0;
        for (int p = 0; p < P; p++)
            if (ba[p] == b) { if (p < s) s = p; e = p + 1; }
        if (e > s) { d_segs[2*b] = s; d_segs[2*b+1] = e; d_hasany[b] = 1; }
        else       { d_segs[2*b] = 0; d_segs[2*b+1] = 0; d_hasany[b] = 0; }
    }
}

// ---------------- k/v projection for the 128 gathered rows ---------------------
__global__ void kv_kernel(const float* __restrict__ Hg, const int* __restrict__ idx,
                          const float* __restrict__ ipw, const float* __restrict__ ipb) {
    __shared__ float hrow[Dd];
    int p = blockIdx.x, t = threadIdx.x;
    hrow[t] = Hg[(size_t)idx[p] * Dd + t];
    __syncthreads();
    const float4* h4 = (const float4*)hrow;
    const float4* wk = (const float4*)(ipw + (size_t)(Dd + t) * Dd);
    const float4* wv = (const float4*)(ipw + (size_t)(2 * Dd + t) * Dd);
    float ak = ipb[Dd + t], av = ipb[2 * Dd + t];
#pragma unroll 16
    for (int c = 0; c < Dd / 4; c++) {
        float4 hv = h4[c]; float4 a = wk[c]; float4 b = wv[c];
        ak += hv.x*a.x + hv.y*a.y + hv.z*a.z + hv.w*a.w;
        av += hv.x*b.x + hv.y*b.y + hv.z*b.z + hv.w*b.w;
    }
    d_k[p * Dd + t] = ak;
    d_v[p * Dd + t] = av;
}

// ---------------- generic SGEMM: C[m,n] = sum_k A[m,k]*B[n,k] + bias[n] --------
// MODE 0: plain   MODE 1: exact gelu   MODE 2: + res[m,n]
template <int MODE>
__global__ __launch_bounds__(256) void sgemm_kernel(
    const float* __restrict__ A, const float* __restrict__ B,
    const float* __restrict__ bias, const float* __restrict__ res,
    float* __restrict__ C, int M, int N, int K)
{
    __shared__ float As[8][128];
    __shared__ float Bs[8][128];
    int m0 = blockIdx.y * 128, n0 = blockIdx.x * 128;
    int tid = threadIdx.x;
    int tx = tid & 15, ty = tid >> 4;
    int lr = tid >> 1;
    int lc = (tid & 1) << 2;
    float acc[8][8] = {};
    const float* Ap = A + (size_t)(m0 + lr) * K + lc;
    const float* Bp = B + (size_t)(n0 + lr) * K + lc;
    bool a_ok = (m0 + lr) < M;
    for (int k0 = 0; k0 < K; k0 += 8) {
        float4 a = a_ok ? *(const float4*)(Ap + k0) : make_float4(0.f, 0.f, 0.f, 0.f);
        float4 b = *(const float4*)(Bp + k0);
        __syncthreads();
        As[lc+0][lr] = a.x; As[lc+1][lr] = a.y; As[lc+2][lr] = a.z; As[lc+3][lr] = a.w;
        Bs[lc+0][lr] = b.x; Bs[lc+1][lr] = b.y; Bs[lc+2][lr] = b.z; Bs[lc+3][lr] = b.w;
        __syncthreads();
#pragma unroll
        for (int kk = 0; kk < 8; kk++) {
            float ar[8], br[8];
            *(float4*)(ar)     = *(const float4*)&As[kk][ty * 8];
            *(float4*)(ar + 4) = *(const float4*)&As[kk][ty * 8 + 4];
            *(float4*)(br)     = *(const float4*)&Bs[kk][tx * 8];
            *(float4*)(br + 4) = *(const float4*)&Bs[kk][tx * 8 + 4];
#pragma unroll
            for (int i = 0; i < 8; i++)
#pragma unroll
                for (int j = 0; j < 8; j++)
                    acc[i][j] += ar[i] * br[j];
        }
    }
#pragma unroll
    for (int i = 0; i < 8; i++) {
        int m = m0 + ty * 8 + i;
        if (m >= M) continue;
#pragma unroll
        for (int j = 0; j < 8; j++) {
            int n = n0 + tx * 8 + j;
            float val = acc[i][j] + bias[n];
            if (MODE == 1) val = 0.5f * val * (1.0f + erff(val * 0.70710678118654752f));
            if (MODE == 2) val += res[(size_t)m * N + n];
            C[(size_t)m * N + n] = val;
        }
    }
}

// ---------------- per-head scores: scale * q_h @ k_h^T -------------------------
__global__ void scores_kernel(int N) {
    int h = blockIdx.y;
    int n0 = blockIdx.x * 64;
    __shared__ float ks[128][33];
    __shared__ float qs[64][33];
    int tid = threadIdx.x;
    for (int i = tid; i < 128 * 32; i += 256) {
        int p = i >> 5, e = i & 31;
        ks[p][e] = d_k[p * Dd + h * DHh + e];
    }
    for (int i = tid; i < 64 * 32; i += 256) {
        int r = i >> 5, e = i & 31;
        int n = n0 + r;
        qs[r][e] = (n < N) ? d_q[(size_t)n * Dd + h * DHh + e] : 0.f;
    }
    __syncthreads();
    int tp = tid & 127, r0 = tid >> 7;
    const float scale = 0.17677669529663687f;  // 1/sqrt(32)
    for (int r = r0; r < 64; r += 2) {
        int n = n0 + r;
        if (n >= N) break;
        float s = 0.f;
#pragma unroll
        for (int e = 0; e < 32; e++) s += qs[r][e] * ks[tp][e];
        d_scores[((size_t)n * Hh + h) * Pmax + tp] = s * scale;
    }
}

// ---------------- segment softmax + ctx accumulation ---------------------------
// one warp per head; block handles 16 n-rows for one batch b
__global__ void attn_kernel(int N) {
    int b = blockIdx.y;
    int h = threadIdx.x >> 5, l = threadIdx.x & 31;
    int s = d_segs[2 * b], e = d_segs[2 * b + 1];
    int L = e - s;
    __shared__ float ws[8][128];
    int nEnd = min(N, (int)(blockIdx.x + 1) * 16);
    for (int n = blockIdx.x * 16; n < nEnd; n++) {
        size_t obase = ((size_t)b * N + n) * Dd + h * DHh;
        if (L <= 0) { d_ctx[obase + l] = 0.f; continue; }
        float sc[4]; int cnt = 0;
        float m = -1e30f;
        for (int pl = l; pl < L; pl += 32) {
            float xv = d_scores[((size_t)n * Hh + h) * Pmax + s + pl];
            sc[cnt++] = xv;
            m = fmaxf(m, xv);
        }
#pragma unroll
        for (int o = 16; o; o >>= 1) m = fmaxf(m, __shfl_xor_sync(0xffffffffu, m, o));
        float sum = 0.f; cnt = 0;
        for (int pl = l; pl < L; pl += 32) {
            float w = __expf(sc[cnt++] - m);
            ws[h][pl] = w;
            sum += w;
        }
#pragma unroll
        for (int o = 16; o; o >>= 1) sum += __shfl_xor_sync(0xffffffffu, sum, o);
        float inv = 1.f / sum;
        __syncwarp();
        float acc = 0.f;
        for (int pl = 0; pl < L; pl++)
            acc += ws[h][pl] * d_v[(size_t)(s + pl) * Dd + h * DHh + l];
        d_ctx[obase + l] = acc * inv;
        __syncwarp();
    }
}

// ---------------- LN1: x = LN(H[n] + has_any[b]*attn_out) ----------------------
__global__ void ln1_kernel(const float* __restrict__ Hg, const float* __restrict__ g,
                           const float* __restrict__ bt, int N, int B) {
    int wid = threadIdx.x >> 5, l = threadIdx.x & 31;
    size_t row = (size_t)blockIdx.x * 8 + wid;
    if (row >= (size_t)B * N) return;
    int b = (int)(row / N), n = (int)(row % N);
    float ha = d_hasany[b] ? 1.f : 0.f;
    float vals[8];
    float sum = 0.f;
#pragma unroll
    for (int j = 0; j < 8; j++) {
        int e2 = l + 32 * j;
        vals[j] = Hg[(size_t)n * Dd + e2] + ha * d_tmp[row * Dd + e2];
        sum += vals[j];
    }
#pragma unroll
    for (int o = 16; o; o >>= 1) sum += __shfl_xor_sync(0xffffffffu, sum, o);
    float mu = sum * (1.f / Dd);
    float s2 = 0.f;
#pragma unroll
    for (int j = 0; j < 8; j++) { float dd = vals[j] - mu; s2 += dd * dd; }
#pragma unroll
    for (int o = 16; o; o >>= 1) s2 += __shfl_xor_sync(0xffffffffu, s2, o);
    float r = rsqrtf(s2 * (1.f / Dd) + 1e-5f);
#pragma unroll
    for (int j = 0; j < 8; j++) {
        int e2 = l + 32 * j;
        d_x[row * Dd + e2] = (vals[j] - mu) * r * g[e2] + bt[e2];
    }
}

// ---------------- LN2: out = LN(y)  (y lives in d_ctx, reused) -----------------
__global__ void ln2_kernel(const float* __restrict__ g, const float* __restrict__ bt,
                           float* __restrict__ out, int N, int B) {
    int wid = threadIdx.x >> 5, l = threadIdx.x & 31;
    size_t row = (size_t)blockIdx.x * 8 + wid;
    if (row >= (size_t)B * N) return;
    float vals[8];
    float sum = 0.f;
#pragma unroll
    for (int j = 0; j < 8; j++) {
        int e2 = l + 32 * j;
        vals[j] = d_ctx[row * Dd + e2];
        sum += vals[j];
    }
#pragma unroll
    for (int o = 16; o; o >>= 1) sum += __shfl_xor_sync(0xffffffffu, sum, o);
    float mu = sum * (1.f / Dd);
    float s2 = 0.f;
#pragma unroll
    for (int j = 0; j < 8; j++) { float dd = vals[j] - mu; s2 += dd * dd; }
#pragma unroll
    for (int o = 16; o; o >>= 1) s2 += __shfl_xor_sync(0xffffffffu, s2, o);
    float r = rsqrtf(s2 * (1.f / Dd) + 1e-5f);
#pragma unroll
    for (int j = 0; j < 8; j++) {
        int e2 = l + 32 * j;
        out[row * Dd + e2] = (vals[j] - mu) * r * g[e2] + bt[e2];
    }
}

// -------------------------------- launch ---------------------------------------
extern "C" void kernel_launch(void* const* d_in, const int* in_sizes, int n_in,
                              void* d_out, int out_size) {
    const float* Hg  = (const float*)d_in[0];
    const int*  pidx = (const int*)d_in[1];
    const int*  ba   = (const int*)d_in[2];
    // d_in[3] = batch_size (derived from out_size instead; no device read needed)
    const float* ipw = (const float*)d_in[4];
    const float* ipb = (const float*)d_in[5];
    const float* opw = (const float*)d_in[6];
    const float* opb = (const float*)d_in[7];
    const float* w1  = (const float*)d_in[8];
    const float* b1  = (const float*)d_in[9];
    const float* w2  = (const float*)d_in[10];
    const float* b2  = (const float*)d_in[11];
    const float* g1  = (const float*)d_in[12];
    const float* be1 = (const float*)d_in[13];
    const float* g2  = (const float*)d_in[14];
    const float* be2 = (const float*)d_in[15];
    float* out = (float*)d_out;

    int N = in_sizes[0] / Dd;          // 6000
    int P = in_sizes[1];               // 128
    int B = out_size / (N * Dd);       // 16
    int M = B * N;                     // 96000

    float *q, *ctx, *tmp, *x, *hidden;
    cudaGetSymbolAddress((void**)&q,      d_q);
    cudaGetSymbolAddress((void**)&ctx,    d_ctx);
    cudaGetSymbolAddress((void**)&tmp,    d_tmp);
    cudaGetSymbolAddress((void**)&x,      d_x);
    cudaGetSymbolAddress((void**)&hidden, d_hidden);

    // 1. batch segments
    seg_kernel<<<1, 1>>>(ba, P, B);
    // 2. k/v projections of gathered rows
    kv_kernel<<<P, Dd>>>(Hg, pidx, ipw, ipb);
    // 3. q = H @ Wq^T + bq
    sgemm_kernel<0><<<dim3(Dd / 128, (N + 127) / 128), 256>>>(Hg, ipw, ipb, nullptr, q, N, Dd, Dd);
    // 4. per-head scores
    scores_kernel<<<dim3((N + 63) / 64, Hh), 256>>>(N);
    // 5. segment softmax + ctx
    attn_kernel<<<dim3((N + 15) / 16, B), 256>>>(N);
    // 6. attn_out = ctx @ Wout^T + bout
    sgemm_kernel<0><<<dim3(Dd / 128, (M + 127) / 128), 256>>>(ctx, opw, opb, nullptr, tmp, M, Dd, Dd);
    // 7. x = LN1(H + has_any * attn_out)
    ln1_kernel<<<(M + 7) / 8, 256>>>(Hg, g1, be1, N, B);
    // 8. hidden = gelu(x @ W1^T + b1)
    sgemm_kernel<1><<<dim3(FF / 128, (M + 127) / 128), 256>>>(x, w1, b1, nullptr, hidden, M, FF, Dd);
    // 9. y = x + hidden @ W2^T + b2   (y -> d_ctx, reused)
    sgemm_kernel<2><<<dim3(Dd / 128, (M + 127) / 128), 256>>>(hidden, w2, b2, x, ctx, M, Dd, FF);
    // 10. out = LN2(y)
    ln2_kernel<<<(M + 7) / 8, 256>>>(g2, be2, out, N, B);
}

// round 3
// speedup vs baseline: 1.8826x; 1.8826x over previous
#include <cuda_runtime.h>
#include <math.h>
#include <stdint.h>

// Problem constants
#define Dd 256
#define Hh 8
#define DHh 32
#define Pmax 128
#define Bmax 16
#define Nmax 6000
#define FF 1024

// ---------------- scratch (static __device__ — no allocation allowed) ----------
__device__ float d_q[Nmax * Dd];
__device__ float d_k[Pmax * Dd];
__device__ float d_v[Pmax * Dd];
__device__ float d_scores[(size_t)Nmax * Hh * Pmax];
__device__ float d_ctx[(size_t)Bmax * Nmax * Dd];     // ctx, later reused as y
__device__ float d_tmp[(size_t)Bmax * Nmax * Dd];     // attn_out
__device__ float d_x[(size_t)Bmax * Nmax * Dd];       // post-LN1 activations
__device__ float d_hidden[(size_t)Bmax * Nmax * FF];  // FFN hidden
__device__ int   d_segs[2 * Bmax];
__device__ int   d_hasany[Bmax];

// ---------------- tf32 helpers --------------------------------------------------
__device__ __forceinline__ float f2tf(float x) {
    uint32_t r; asm("cvt.rna.tf32.f32 %0, %1;" : "=r"(r) : "f"(x));
    return __uint_as_float(r);
}

#define MMA_TF32(d, a, b)                                                         \
    asm volatile("mma.sync.aligned.m16n8k8.row.col.f32.tf32.tf32.f32 "            \
        "{%0,%1,%2,%3},{%4,%5,%6,%7},{%8,%9},{%0,%1,%2,%3};"                      \
        : "+f"((d)[0]), "+f"((d)[1]), "+f"((d)[2]), "+f"((d)[3])                   \
        : "r"((a).x), "r"((a).y), "r"((a).z), "r"((a).w), "r"((b).x), "r"((b).y))

// ======================= tensor-core tf32 GEMM ==================================
// C[m,n] = sum_k A[m,k]*B[n,k] + bias[n];  MODE 0 plain, 1 exact gelu, 2 +res[m,n]
// Block tile 128(M) x 128(N); 8 warps, each 64x32; K-chunk 32; double-buffered.
// Smem (floats): A buf: buf*4096 .. fragment-packed; B buf: 8192 + buf*4096.
//   A frag addr: ((ksub*8 + mtile)*32 + lane)*4 + reg   (reg = (c%8>=4)*2 + (r%16>=8))
//   B frag addr: ((ksub*16 + ntile)*32 + lane)*2 + reg  (reg = (k%8>=4))
#define SMEM_SZ 65536

template <int MODE>
__global__ __launch_bounds__(256, 1) void tgemm(
    const float* __restrict__ A, const float* __restrict__ B,
    const float* __restrict__ bias, const float* __restrict__ res,
    float* __restrict__ C, int M, int Nn, int K)
{
    extern __shared__ __align__(16) float sm[];
    int tid = threadIdx.x, wid = tid >> 5, lane = tid & 31;
    int m0 = blockIdx.y * 128, n0 = blockIdx.x * 128;
    int wm = wid & 1, wn = wid >> 1;          // warp tile: rows wm*64, cols wn*32
    int nch = K >> 5;

    int r = tid >> 3, c4 = tid & 7;           // loader coords
    int ksub = c4 >> 1;

    float4 ra[4], rb[4];

    auto ldg_chunk = [&](int c) {
        int k0 = c << 5;
#pragma unroll
        for (int j = 0; j < 4; j++) {
            int row = r + 32 * j;
            ra[j] = (m0 + row < M) ? *(const float4*)(A + (size_t)(m0 + row) * K + k0 + c4 * 4)
                                   : make_float4(0.f, 0.f, 0.f, 0.f);
            rb[j] = *(const float4*)(B + (size_t)(n0 + row) * K + k0 + c4 * 4);
        }
    };
    auto sts_chunk = [&](int buf) {
        float* sa = sm + buf * 4096;
        float* sb = sm + 8192 + buf * 4096;
#pragma unroll
        for (int j = 0; j < 4; j++) {
            int row = r + 32 * j;
            // A fragment scatter
            int mtile = row >> 4, rlo = row & 7, rhid = (row >> 3) & 1;
            float* ab = sa + (((ksub * 8 + mtile) * 32 + rlo * 4) * 4) + ((c4 & 1) * 2 + rhid);
            ab[0]  = f2tf(ra[j].x);
            ab[4]  = f2tf(ra[j].y);
            ab[8]  = f2tf(ra[j].z);
            ab[12] = f2tf(ra[j].w);
            // B fragment scatter
            int ntile = row >> 3, nlo = row & 7;
            float* bb = sb + (((ksub * 16 + ntile) * 32 + nlo * 4) * 2) + (c4 & 1);
            bb[0] = f2tf(rb[j].x);
            bb[2] = f2tf(rb[j].y);
            bb[4] = f2tf(rb[j].z);
            bb[6] = f2tf(rb[j].w);
        }
    };

    float acc[16][4] = {};

    auto compute = [&](int buf) {
        const float* sa = sm + buf * 4096;
        const float* sb = sm + 8192 + buf * 4096;
#pragma unroll
        for (int ks = 0; ks < 4; ks++) {
            uint4 af[4]; uint2 bf[4];
#pragma unroll
            for (int i = 0; i < 4; i++)
                af[i] = *(const uint4*)(sa + ((ks * 8 + wm * 4 + i) * 32 + lane) * 4);
#pragma unroll
            for (int i = 0; i < 4; i++)
                bf[i] = *(const uint2*)(sb + ((ks * 16 + wn * 4 + i) * 32 + lane) * 2);
#pragma unroll
            for (int i = 0; i < 4; i++)
#pragma unroll
                for (int j = 0; j < 4; j++)
                    MMA_TF32(acc[i * 4 + j], af[i], bf[j]);
        }
    };

    ldg_chunk(0);
    sts_chunk(0);
    for (int c = 0; c < nch; c++) {
        __syncthreads();
        if (c + 1 < nch) ldg_chunk(c + 1);
        compute(c & 1);
        if (c + 1 < nch) sts_chunk((c + 1) & 1);
    }

    // --- epilogue from register accumulators ---
    int g = lane >> 2, q4 = lane & 3;
#pragma unroll
    for (int i = 0; i < 4; i++) {
#pragma unroll
        for (int j = 0; j < 4; j++) {
            int col = n0 + (wn * 4 + j) * 8 + q4 * 2;
            float b0 = bias[col], b1 = bias[col + 1];
            const float* a4 = acc[i * 4 + j];
#pragma unroll
            for (int half = 0; half < 2; half++) {
                int mrow = m0 + (wm * 4 + i) * 16 + g + half * 8;
                if (mrow >= M) continue;
                float v0 = a4[half * 2 + 0] + b0;
                float v1 = a4[half * 2 + 1] + b1;
                if (MODE == 1) {
                    const float kk = 0.70710678118654752f;
                    v0 = 0.5f * v0 * (1.f + erff(v0 * kk));
                    v1 = 0.5f * v1 * (1.f + erff(v1 * kk));
                }
                if (MODE == 2) {
                    const float* Rp = res + (size_t)mrow * Nn + col;
                    v0 += Rp[0]; v1 += Rp[1];
                }
                *(float2*)(C + (size_t)mrow * Nn + col) = make_float2(v0, v1);
            }
        }
    }
}

// ---------------- segment scan (batch_assignment is sorted) --------------------
__global__ void seg_kernel(const int* __restrict__ ba, int P, int B) {
    if (threadIdx.x != 0 || blockIdx.x != 0) return;
    for (int b = 0; b < B; b++) {
        int s = P, e = 0;
        for (int p = 0; p < P; p++)
            if (ba[p] == b) { if (p < s) s = p; e = p + 1; }
        if (e > s) { d_segs[2*b] = s; d_segs[2*b+1] = e; d_hasany[b] = 1; }
        else       { d_segs[2*b] = 0; d_segs[2*b+1] = 0; d_hasany[b] = 0; }
    }
}

// ---------------- k/v projection for the 128 gathered rows ---------------------
__global__ void kv_kernel(const float* __restrict__ Hg, const int* __restrict__ idx,
                          const float* __restrict__ ipw, const float* __restrict__ ipb) {
    __shared__ float hrow[Dd];
    int p = blockIdx.x, t = threadIdx.x;
    hrow[t] = Hg[(size_t)idx[p] * Dd + t];
    __syncthreads();
    const float4* h4 = (const float4*)hrow;
    const float4* wk = (const float4*)(ipw + (size_t)(Dd + t) * Dd);
    const float4* wv = (const float4*)(ipw + (size_t)(2 * Dd + t) * Dd);
    float ak = ipb[Dd + t], av = ipb[2 * Dd + t];
#pragma unroll 16
    for (int c = 0; c < Dd / 4; c++) {
        float4 hv = h4[c]; float4 a = wk[c]; float4 b = wv[c];
        ak += hv.x*a.x + hv.y*a.y + hv.z*a.z + hv.w*a.w;
        av += hv.x*b.x + hv.y*b.y + hv.z*b.z + hv.w*b.w;
    }
    d_k[p * Dd + t] = ak;
    d_v[p * Dd + t] = av;
}

// ---------------- per-head scores: scale * q_h @ k_h^T -------------------------
__global__ void scores_kernel(int N) {
    int h = blockIdx.y;
    int n0 = blockIdx.x * 64;
    __shared__ float ks[128][33];
    __shared__ float qs[64][33];
    int tid = threadIdx.x;
    for (int i = tid; i < 128 * 32; i += 256) {
        int p = i >> 5, e = i & 31;
        ks[p][e] = d_k[p * Dd + h * DHh + e];
    }
    for (int i = tid; i < 64 * 32; i += 256) {
        int r = i >> 5, e = i & 31;
        int n = n0 + r;
        qs[r][e] = (n < N) ? d_q[(size_t)n * Dd + h * DHh + e] : 0.f;
    }
    __syncthreads();
    int tp = tid & 127, r0 = tid >> 7;
    const float scale = 0.17677669529663687f;  // 1/sqrt(32)
    for (int r = r0; r < 64; r += 2) {
        int n = n0 + r;
        if (n >= N) break;
        float s = 0.f;
#pragma unroll
        for (int e = 0; e < 32; e++) s += qs[r][e] * ks[tp][e];
        d_scores[((size_t)n * Hh + h) * Pmax + tp] = s * scale;
    }
}

// ---------------- segment softmax + ctx accumulation ---------------------------
__global__ void attn_kernel(int N) {
    int b = blockIdx.y;
    int h = threadIdx.x >> 5, l = threadIdx.x & 31;
    int s = d_segs[2 * b], e = d_segs[2 * b + 1];
    int L = e - s;
    __shared__ float ws[8][128];
    int nEnd = min(N, (int)(blockIdx.x + 1) * 16);
    for (int n = blockIdx.x * 16; n < nEnd; n++) {
        size_t obase = ((size_t)b * N + n) * Dd + h * DHh;
        if (L <= 0) { d_ctx[obase + l] = 0.f; continue; }
        float sc[4]; int cnt = 0;
        float m = -1e30f;
        for (int pl = l; pl < L; pl += 32) {
            float xv = d_scores[((size_t)n * Hh + h) * Pmax + s + pl];
            sc[cnt++] = xv;
            m = fmaxf(m, xv);
        }
#pragma unroll
        for (int o = 16; o; o >>= 1) m = fmaxf(m, __shfl_xor_sync(0xffffffffu, m, o));
        float sum = 0.f; cnt = 0;
        for (int pl = l; pl < L; pl += 32) {
            float w = __expf(sc[cnt++] - m);
            ws[h][pl] = w;
            sum += w;
        }
#pragma unroll
        for (int o = 16; o; o >>= 1) sum += __shfl_xor_sync(0xffffffffu, sum, o);
        float inv = 1.f / sum;
        __syncwarp();
        float acc = 0.f;
        for (int pl = 0; pl < L; pl++)
            acc += ws[h][pl] * d_v[(size_t)(s + pl) * Dd + h * DHh + l];
        d_ctx[obase + l] = acc * inv;
        __syncwarp();
    }
}

// ---------------- LN1: x = LN(H[n] + has_any[b]*attn_out) ----------------------
__global__ void ln1_kernel(const float* __restrict__ Hg, const float* __restrict__ g,
                           const float* __restrict__ bt, int N, int B) {
    int wid = threadIdx.x >> 5, l = threadIdx.x & 31;
    size_t row = (size_t)blockIdx.x * 8 + wid;
    if (row >= (size_t)B * N) return;
    int b = (int)(row / N), n = (int)(row % N);
    float ha = d_hasany[b] ? 1.f : 0.f;
    float vals[8];
    float sum = 0.f;
#pragma unroll
    for (int j = 0; j < 8; j++) {
        int e2 = l + 32 * j;
        vals[j] = Hg[(size_t)n * Dd + e2] + ha * d_tmp[row * Dd + e2];
        sum += vals[j];
    }
#pragma unroll
    for (int o = 16; o; o >>= 1) sum += __shfl_xor_sync(0xffffffffu, sum, o);
    float mu = sum * (1.f / Dd);
    float s2 = 0.f;
#pragma unroll
    for (int j = 0; j < 8; j++) { float dd = vals[j] - mu; s2 += dd * dd; }
#pragma unroll
    for (int o = 16; o; o >>= 1) s2 += __shfl_xor_sync(0xffffffffu, s2, o);
    float r = rsqrtf(s2 * (1.f / Dd) + 1e-5f);
#pragma unroll
    for (int j = 0; j < 8; j++) {
        int e2 = l + 32 * j;
        d_x[row * Dd + e2] = (vals[j] - mu) * r * g[e2] + bt[e2];
    }
}

// ---------------- LN2: out = LN(y) ---------------------------------------------
__global__ void ln2_kernel(const float* __restrict__ g, const float* __restrict__ bt,
                           float* __restrict__ out, int N, int B) {
    int wid = threadIdx.x >> 5, l = threadIdx.x & 31;
    size_t row = (size_t)blockIdx.x * 8 + wid;
    if (row >= (size_t)B * N) return;
    float vals[8];
    float sum = 0.f;
#pragma unroll
    for (int j = 0; j < 8; j++) {
        int e2 = l + 32 * j;
        vals[j] = d_ctx[row * Dd + e2];
        sum += vals[j];
    }
#pragma unroll
    for (int o = 16; o; o >>= 1) sum += __shfl_xor_sync(0xffffffffu, sum, o);
    float mu = sum * (1.f / Dd);
    float s2 = 0.f;
#pragma unroll
    for (int j = 0; j < 8; j++) { float dd = vals[j] - mu; s2 += dd * dd; }
#pragma unroll
    for (int o = 16; o; o >>= 1) s2 += __shfl_xor_sync(0xffffffffu, s2, o);
    float r = rsqrtf(s2 * (1.f / Dd) + 1e-5f);
#pragma unroll
    for (int j = 0; j < 8; j++) {
        int e2 = l + 32 * j;
        out[row * Dd + e2] = (vals[j] - mu) * r * g[e2] + bt[e2];
    }
}

// -------------------------------- launch ---------------------------------------
extern "C" void kernel_launch(void* const* d_in, const int* in_sizes, int n_in,
                              void* d_out, int out_size) {
    const float* Hg  = (const float*)d_in[0];
    const int*  pidx = (const int*)d_in[1];
    const int*  ba   = (const int*)d_in[2];
    const float* ipw = (const float*)d_in[4];
    const float* ipb = (const float*)d_in[5];
    const float* opw = (const float*)d_in[6];
    const float* opb = (const float*)d_in[7];
    const float* w1  = (const float*)d_in[8];
    const float* b1  = (const float*)d_in[9];
    const float* w2  = (const float*)d_in[10];
    const float* b2  = (const float*)d_in[11];
    const float* g1  = (const float*)d_in[12];
    const float* be1 = (const float*)d_in[13];
    const float* g2  = (const float*)d_in[14];
    const float* be2 = (const float*)d_in[15];
    float* out = (float*)d_out;

    int N = in_sizes[0] / Dd;          // 6000
    int P = in_sizes[1];               // 128
    int B = out_size / (N * Dd);       // 16
    int M = B * N;                     // 96000

    float *q, *ctx, *tmp, *x, *hidden;
    cudaGetSymbolAddress((void**)&q,      d_q);
    cudaGetSymbolAddress((void**)&ctx,    d_ctx);
    cudaGetSymbolAddress((void**)&tmp,    d_tmp);
    cudaGetSymbolAddress((void**)&x,      d_x);
    cudaGetSymbolAddress((void**)&hidden, d_hidden);

    cudaFuncSetAttribute(tgemm<0>, cudaFuncAttributeMaxDynamicSharedMemorySize, SMEM_SZ);
    cudaFuncSetAttribute(tgemm<1>, cudaFuncAttributeMaxDynamicSharedMemorySize, SMEM_SZ);
    cudaFuncSetAttribute(tgemm<2>, cudaFuncAttributeMaxDynamicSharedMemorySize, SMEM_SZ);

    // 1. batch segments
    seg_kernel<<<1, 1>>>(ba, P, B);
    // 2. k/v projections of gathered rows
    kv_kernel<<<P, Dd>>>(Hg, pidx, ipw, ipb);
    // 3. q = H @ Wq^T + bq  (tensor tf32)
    tgemm<0><<<dim3(Dd / 128, (N + 127) / 128), 256, SMEM_SZ>>>(Hg, ipw, ipb, nullptr, q, N, Dd, Dd);
    // 4. per-head scores
    scores_kernel<<<dim3((N + 63) / 64, Hh), 256>>>(N);
    // 5. segment softmax + ctx
    attn_kernel<<<dim3((N + 15) / 16, B), 256>>>(N);
    // 6. attn_out = ctx @ Wout^T + bout  (tensor tf32)
    tgemm<0><<<dim3(Dd / 128, (M + 127) / 128), 256, SMEM_SZ>>>(ctx, opw, opb, nullptr, tmp, M, Dd, Dd);
    // 7. x = LN1(H + has_any * attn_out)
    ln1_kernel<<<(M + 7) / 8, 256>>>(Hg, g1, be1, N, B);
    // 8. hidden = gelu(x @ W1^T + b1)  (tensor tf32)
    tgemm<1><<<dim3(FF / 128, (M + 127) / 128), 256, SMEM_SZ>>>(x, w1, b1, nullptr, hidden, M, FF, Dd);
    // 9. y = x + hidden @ W2^T + b2  (tensor tf32; y -> d_ctx reused)
    tgemm<2><<<dim3(Dd / 128, (M + 127) / 128), 256, SMEM_SZ>>>(hidden, w2, b2, x, ctx, M, Dd, FF);
    // 10. out = LN2(y)
    ln2_kernel<<<(M + 7) / 8, 256>>>(g2, be2, out, N, B);
}

// round 4
// speedup vs baseline: 2.8362x; 1.5065x over previous
#include <cuda_runtime.h>
#include <math.h>
#include <stdint.h>

// Problem constants
#define Dd 256
#define Hh 8
#define DHh 32
#define Pmax 128
#define Bmax 16
#define Nmax 6000
#define FF 1024

// ---------------- scratch (static __device__ — no allocation allowed) ----------
__device__ float d_q[Nmax * Dd];
__device__ float d_k[Pmax * Dd];
__device__ float d_v[Pmax * Dd];
__device__ float d_scores[(size_t)Nmax * Hh * Pmax];
__device__ float d_ctx[(size_t)Bmax * Nmax * Dd];     // ctx, later reused as y
__device__ float d_tmp[(size_t)Bmax * Nmax * Dd];     // attn_out
__device__ float d_x[(size_t)Bmax * Nmax * Dd];       // post-LN1 activations
__device__ float d_hidden[(size_t)Bmax * Nmax * FF];  // FFN hidden
__device__ int   d_segs[2 * Bmax];
__device__ int   d_hasany[Bmax];

// ---------------- helpers -------------------------------------------------------
__device__ __forceinline__ uint32_t smem_u32(const void* p) {
    uint32_t a;
    asm("{ .reg .u64 t; cvta.to.shared.u64 t, %1; cvt.u32.u64 %0, t; }" : "=r"(a) : "l"(p));
    return a;
}

#define MMA_TF32(d, A0, A1, A2, A3, B0, B1)                                       \
    asm volatile("mma.sync.aligned.m16n8k8.row.col.f32.tf32.tf32.f32 "            \
        "{%0,%1,%2,%3},{%4,%5,%6,%7},{%8,%9},{%0,%1,%2,%3};"                      \
        : "+f"((d)[0]), "+f"((d)[1]), "+f"((d)[2]), "+f"((d)[3])                   \
        : "r"(A0), "r"(A1), "r"(A2), "r"(A3), "r"(B0), "r"(B1))

// ======================= tensor-core tf32 GEMM (cp.async) =======================
// C[m,n] = sum_k A[m,k]*B[n,k] + bias[n];  MODE 0 plain, 1 exact gelu, 2 +res[m,n]
// Block tile 128(M) x 128(N); 8 warps, each 64x32; K-chunk 32; 2-stage cp.async.
// Smem stage s: A at s*16KB, B at 32KB + s*16KB. 128B rows, XOR-granule swizzle.
#define SMEM_SZ 65536

template <int MODE>
__global__ __launch_bounds__(256, 1) void tgemm(
    const float* __restrict__ A, const float* __restrict__ B,
    const float* __restrict__ bias, const float* __restrict__ res,
    float* __restrict__ C, int M, int Nn, int K)
{
    extern __shared__ __align__(128) float sm[];
    uint32_t sbase = smem_u32(sm);
    int tid = threadIdx.x, wid = tid >> 5, lane = tid & 31;
    int m0 = blockIdx.y * 128, n0 = blockIdx.x * 128;
    int wm = wid & 1, wn = wid >> 1;          // warp tile: rows wm*64, cols wn*32
    int nch = K >> 5;

    // ---- async stage loader: 128 rows x 32 floats per matrix, raw fp32 ----
    auto issue_stage = [&](int c) {
        int k0 = c << 5;
        uint32_t sa = sbase + (uint32_t)(c & 1) * 16384u;
        uint32_t sb = sbase + 32768u + (uint32_t)(c & 1) * 16384u;
#pragma unroll
        for (int j = 0; j < 4; j++) {
            int seg = tid + j * 256;
            int r = seg >> 3, kk = (seg & 7) << 2;           // float col in chunk
            uint32_t off = (uint32_t)(r * 128 + kk * 4);
            off ^= (uint32_t)(r & 7) << 4;
            int arow = m0 + r;
            const float* gA = A + (size_t)(arow < M ? arow : M - 1) * K + k0 + kk;
            int szA = (arow < M) ? 16 : 0;
            asm volatile("cp.async.cg.shared.global [%0], [%1], 16, %2;"
                         :: "r"(sa + off), "l"(gA), "r"(szA));
            const float* gB = B + (size_t)(n0 + r) * K + k0 + kk;
            asm volatile("cp.async.cg.shared.global [%0], [%1], 16;"
                         :: "r"(sb + off), "l"(gB));
        }
        asm volatile("cp.async.commit_group;" ::: "memory");
    };

    float acc[16][4] = {};
    int rl = lane >> 2, cc = lane & 3;

    auto compute = [&](int buf) {
        const uint32_t* sa = (const uint32_t*)(sm + buf * 4096);
        const uint32_t* sb = (const uint32_t*)(sm + 8192 + buf * 4096);
#pragma unroll
        for (int ks = 0; ks < 4; ks++) {
            int g0 = (((2 * ks) ^ rl) << 2) + cc;
            int g1 = (((2 * ks + 1) ^ rl) << 2) + cc;
            uint32_t af[4][4];
#pragma unroll
            for (int i = 0; i < 4; i++) {
                int row = wm * 64 + i * 16 + rl;
                af[i][0] = sa[row * 32 + g0];
                af[i][1] = sa[(row + 8) * 32 + g0];
                af[i][2] = sa[row * 32 + g1];
                af[i][3] = sa[(row + 8) * 32 + g1];
            }
            uint32_t bf[4][2];
#pragma unroll
            for (int j = 0; j < 4; j++) {
                int n = wn * 32 + j * 8 + rl;
                bf[j][0] = sb[n * 32 + g0];
                bf[j][1] = sb[n * 32 + g1];
            }
#pragma unroll
            for (int i = 0; i < 4; i++)
#pragma unroll
                for (int j = 0; j < 4; j++)
                    MMA_TF32(acc[i * 4 + j], af[i][0], af[i][1], af[i][2], af[i][3],
                             bf[j][0], bf[j][1]);
        }
    };

    issue_stage(0);
    issue_stage(1);
    for (int c = 0; c < nch; c++) {
        asm volatile("cp.async.wait_group 1;" ::: "memory");
        __syncthreads();
        compute(c & 1);
        __syncthreads();
        if (c + 2 < nch) issue_stage(c + 2);
        else asm volatile("cp.async.commit_group;" ::: "memory");
    }

    // --- epilogue from register accumulators ---
    int g = lane >> 2, q4 = lane & 3;
#pragma unroll
    for (int i = 0; i < 4; i++) {
#pragma unroll
        for (int j = 0; j < 4; j++) {
            int col = n0 + (wn * 4 + j) * 8 + q4 * 2;
            float b0 = bias[col], b1 = bias[col + 1];
            const float* a4 = acc[i * 4 + j];
#pragma unroll
            for (int half = 0; half < 2; half++) {
                int mrow = m0 + (wm * 4 + i) * 16 + g + half * 8;
                if (mrow >= M) continue;
                float v0 = a4[half * 2 + 0] + b0;
                float v1 = a4[half * 2 + 1] + b1;
                if (MODE == 1) {
                    const float kk = 0.70710678118654752f;
                    v0 = 0.5f * v0 * (1.f + erff(v0 * kk));
                    v1 = 0.5f * v1 * (1.f + erff(v1 * kk));
                }
                if (MODE == 2) {
                    const float* Rp = res + (size_t)mrow * Nn + col;
                    v0 += Rp[0]; v1 += Rp[1];
                }
                *(float2*)(C + (size_t)mrow * Nn + col) = make_float2(v0, v1);
            }
        }
    }
}

// ---------------- segment scan (batch_assignment is sorted) --------------------
__global__ void seg_kernel(const int* __restrict__ ba, int P, int B) {
    if (threadIdx.x != 0 || blockIdx.x != 0) return;
    for (int b = 0; b < B; b++) {
        int s = P, e = 0;
        for (int p = 0; p < P; p++)
            if (ba[p] == b) { if (p < s) s = p; e = p + 1; }
        if (e > s) { d_segs[2*b] = s; d_segs[2*b+1] = e; d_hasany[b] = 1; }
        else       { d_segs[2*b] = 0; d_segs[2*b+1] = 0; d_hasany[b] = 0; }
    }
}

// ---------------- k/v projection for the 128 gathered rows ---------------------
__global__ void kv_kernel(const float* __restrict__ Hg, const int* __restrict__ idx,
                          const float* __restrict__ ipw, const float* __restrict__ ipb) {
    __shared__ float hrow[Dd];
    int p = blockIdx.x, t = threadIdx.x;
    hrow[t] = Hg[(size_t)idx[p] * Dd + t];
    __syncthreads();
    const float4* h4 = (const float4*)hrow;
    const float4* wk = (const float4*)(ipw + (size_t)(Dd + t) * Dd);
    const float4* wv = (const float4*)(ipw + (size_t)(2 * Dd + t) * Dd);
    float ak = ipb[Dd + t], av = ipb[2 * Dd + t];
#pragma unroll 16
    for (int c = 0; c < Dd / 4; c++) {
        float4 hv = h4[c]; float4 a = wk[c]; float4 b = wv[c];
        ak += hv.x*a.x + hv.y*a.y + hv.z*a.z + hv.w*a.w;
        av += hv.x*b.x + hv.y*b.y + hv.z*b.z + hv.w*b.w;
    }
    d_k[p * Dd + t] = ak;
    d_v[p * Dd + t] = av;
}

// ---------------- per-head scores: scale * q_h @ k_h^T -------------------------
__global__ void scores_kernel(int N) {
    int h = blockIdx.y;
    int n0 = blockIdx.x * 64;
    __shared__ float ks[128][33];
    __shared__ float qs[64][33];
    int tid = threadIdx.x;
    for (int i = tid; i < 128 * 32; i += 256) {
        int p = i >> 5, e = i & 31;
        ks[p][e] = d_k[p * Dd + h * DHh + e];
    }
    for (int i = tid; i < 64 * 32; i += 256) {
        int r = i >> 5, e = i & 31;
        int n = n0 + r;
        qs[r][e] = (n < N) ? d_q[(size_t)n * Dd + h * DHh + e] : 0.f;
    }
    __syncthreads();
    int tp = tid & 127, r0 = tid >> 7;
    const float scale = 0.17677669529663687f;  // 1/sqrt(32)
    for (int r = r0; r < 64; r += 2) {
        int n = n0 + r;
        if (n >= N) break;
        float s = 0.f;
#pragma unroll
        for (int e = 0; e < 32; e++) s += qs[r][e] * ks[tp][e];
        d_scores[((size_t)n * Hh + h) * Pmax + tp] = s * scale;
    }
}

// ---------------- segment softmax + ctx accumulation ---------------------------
__global__ void attn_kernel(int N) {
    int b = blockIdx.y;
    int h = threadIdx.x >> 5, l = threadIdx.x & 31;
    int s = d_segs[2 * b], e = d_segs[2 * b + 1];
    int L = e - s;
    __shared__ float ws[8][128];
    int nEnd = min(N, (int)(blockIdx.x + 1) * 16);
    for (int n = blockIdx.x * 16; n < nEnd; n++) {
        size_t obase = ((size_t)b * N + n) * Dd + h * DHh;
        if (L <= 0) { d_ctx[obase + l] = 0.f; continue; }
        float sc[4]; int cnt = 0;
        float m = -1e30f;
        for (int pl = l; pl < L; pl += 32) {
            float xv = d_scores[((size_t)n * Hh + h) * Pmax + s + pl];
            sc[cnt++] = xv;
            m = fmaxf(m, xv);
        }
#pragma unroll
        for (int o = 16; o; o >>= 1) m = fmaxf(m, __shfl_xor_sync(0xffffffffu, m, o));
        float sum = 0.f; cnt = 0;
        for (int pl = l; pl < L; pl += 32) {
            float w = __expf(sc[cnt++] - m);
            ws[h][pl] = w;
            sum += w;
        }
#pragma unroll
        for (int o = 16; o; o >>= 1) sum += __shfl_xor_sync(0xffffffffu, sum, o);
        float inv = 1.f / sum;
        __syncwarp();
        float acc = 0.f;
        for (int pl = 0; pl < L; pl++)
            acc += ws[h][pl] * d_v[(size_t)(s + pl) * Dd + h * DHh + l];
        d_ctx[obase + l] = acc * inv;
        __syncwarp();
    }
}

// ---------------- LN1: x = LN(H[n] + has_any[b]*attn_out) ----------------------
__global__ void ln1_kernel(const float* __restrict__ Hg, const float* __restrict__ g,
                           const float* __restrict__ bt, int N, int B) {
    int wid = threadIdx.x >> 5, l = threadIdx.x & 31;
    size_t row = (size_t)blockIdx.x * 8 + wid;
    if (row >= (size_t)B * N) return;
    int b = (int)(row / N), n = (int)(row % N);
    float ha = d_hasany[b] ? 1.f : 0.f;
    float vals[8];
    float sum = 0.f;
#pragma unroll
    for (int j = 0; j < 8; j++) {
        int e2 = l + 32 * j;
        vals[j] = Hg[(size_t)n * Dd + e2] + ha * d_tmp[row * Dd + e2];
        sum += vals[j];
    }
#pragma unroll
    for (int o = 16; o; o >>= 1) sum += __shfl_xor_sync(0xffffffffu, sum, o);
    float mu = sum * (1.f / Dd);
    float s2 = 0.f;
#pragma unroll
    for (int j = 0; j < 8; j++) { float dd = vals[j] - mu; s2 += dd * dd; }
#pragma unroll
    for (int o = 16; o; o >>= 1) s2 += __shfl_xor_sync(0xffffffffu, s2, o);
    float r = rsqrtf(s2 * (1.f / Dd) + 1e-5f);
#pragma unroll
    for (int j = 0; j < 8; j++) {
        int e2 = l + 32 * j;
        d_x[row * Dd + e2] = (vals[j] - mu) * r * g[e2] + bt[e2];
    }
}

// ---------------- LN2: out = LN(y) ---------------------------------------------
__global__ void ln2_kernel(const float* __restrict__ g, const float* __restrict__ bt,
                           float* __restrict__ out, int N, int B) {
    int wid = threadIdx.x >> 5, l = threadIdx.x & 31;
    size_t row = (size_t)blockIdx.x * 8 + wid;
    if (row >= (size_t)B * N) return;
    float vals[8];
    float sum = 0.f;
#pragma unroll
    for (int j = 0; j < 8; j++) {
        int e2 = l + 32 * j;
        vals[j] = d_ctx[row * Dd + e2];
        sum += vals[j];
    }
#pragma unroll
    for (int o = 16; o; o >>= 1) sum += __shfl_xor_sync(0xffffffffu, sum, o);
    float mu = sum * (1.f / Dd);
    float s2 = 0.f;
#pragma unroll
    for (int j = 0; j < 8; j++) { float dd = vals[j] - mu; s2 += dd * dd; }
#pragma unroll
    for (int o = 16; o; o >>= 1) s2 += __shfl_xor_sync(0xffffffffu, s2, o);
    float r = rsqrtf(s2 * (1.f / Dd) + 1e-5f);
#pragma unroll
    for (int j = 0; j < 8; j++) {
        int e2 = l + 32 * j;
        out[row * Dd + e2] = (vals[j] - mu) * r * g[e2] + bt[e2];
    }
}

// -------------------------------- launch ---------------------------------------
extern "C" void kernel_launch(void* const* d_in, const int* in_sizes, int n_in,
                              void* d_out, int out_size) {
    const float* Hg  = (const float*)d_in[0];
    const int*  pidx = (const int*)d_in[1];
    const int*  ba   = (const int*)d_in[2];
    const float* ipw = (const float*)d_in[4];
    const float* ipb = (const float*)d_in[5];
    const float* opw = (const float*)d_in[6];
    const float* opb = (const float*)d_in[7];
    const float* w1  = (const float*)d_in[8];
    const float* b1  = (const float*)d_in[9];
    const float* w2  = (const float*)d_in[10];
    const float* b2  = (const float*)d_in[11];
    const float* g1  = (const float*)d_in[12];
    const float* be1 = (const float*)d_in[13];
    const float* g2  = (const float*)d_in[14];
    const float* be2 = (const float*)d_in[15];
    float* out = (float*)d_out;

    int N = in_sizes[0] / Dd;          // 6000
    int P = in_sizes[1];               // 128
    int B = out_size / (N * Dd);       // 16
    int M = B * N;                     // 96000

    float *q, *ctx, *tmp, *x, *hidden;
    cudaGetSymbolAddress((void**)&q,      d_q);
    cudaGetSymbolAddress((void**)&ctx,    d_ctx);
    cudaGetSymbolAddress((void**)&tmp,    d_tmp);
    cudaGetSymbolAddress((void**)&x,      d_x);
    cudaGetSymbolAddress((void**)&hidden, d_hidden);

    cudaFuncSetAttribute(tgemm<0>, cudaFuncAttributeMaxDynamicSharedMemorySize, SMEM_SZ);
    cudaFuncSetAttribute(tgemm<1>, cudaFuncAttributeMaxDynamicSharedMemorySize, SMEM_SZ);
    cudaFuncSetAttribute(tgemm<2>, cudaFuncAttributeMaxDynamicSharedMemorySize, SMEM_SZ);

    // 1. batch segments
    seg_kernel<<<1, 1>>>(ba, P, B);
    // 2. k/v projections of gathered rows
    kv_kernel<<<P, Dd>>>(Hg, pidx, ipw, ipb);
    // 3. q = H @ Wq^T + bq  (tensor tf32)
    tgemm<0><<<dim3(Dd / 128, (N + 127) / 128), 256, SMEM_SZ>>>(Hg, ipw, ipb, nullptr, q, N, Dd, Dd);
    // 4. per-head scores
    scores_kernel<<<dim3((N + 63) / 64, Hh), 256>>>(N);
    // 5. segment softmax + ctx
    attn_kernel<<<dim3((N + 15) / 16, B), 256>>>(N);
    // 6. attn_out = ctx @ Wout^T + bout  (tensor tf32)
    tgemm<0><<<dim3(Dd / 128, (M + 127) / 128), 256, SMEM_SZ>>>(ctx, opw, opb, nullptr, tmp, M, Dd, Dd);
    // 7. x = LN1(H + has_any * attn_out)
    ln1_kernel<<<(M + 7) / 8, 256>>>(Hg, g1, be1, N, B);
    // 8. hidden = gelu(x @ W1^T + b1)  (tensor tf32)
    tgemm<1><<<dim3(FF / 128, (M + 127) / 128), 256, SMEM_SZ>>>(x, w1, b1, nullptr, hidden, M, FF, Dd);
    // 9. y = x + hidden @ W2^T + b2  (tensor tf32; y -> d_ctx reused)
    tgemm<2><<<dim3(Dd / 128, (M + 127) / 128), 256, SMEM_SZ>>>(hidden, w2, b2, x, ctx, M, Dd, FF);
    // 10. out = LN2(y)
    ln2_kernel<<<(M + 7) / 8, 256>>>(g2, be2, out, N, B);
}

// round 5
// speedup vs baseline: 3.3631x; 1.1858x over previous
#include <cuda_runtime.h>
#include <math.h>
#include <stdint.h>

// Problem constants
#define Dd 256
#define Hh 8
#define DHh 32
#define Pmax 128
#define Bmax 16
#define Nmax 6000
#define FF 1024

// ---------------- scratch (static __device__ — no allocation allowed) ----------
__device__ float d_q[Nmax * Dd];
__device__ float d_k[Pmax * Dd];
__device__ float d_v[Pmax * Dd];
__device__ float d_scores[(size_t)Nmax * Hh * Pmax];
__device__ float d_ctx[(size_t)Bmax * Nmax * Dd];     // attention context
__device__ float d_x[(size_t)Bmax * Nmax * Dd];       // post-LN1 activations
__device__ float d_hidden[(size_t)Bmax * Nmax * FF];  // FFN hidden
__device__ int   d_segs[2 * Bmax];
__device__ int   d_hasany[Bmax];

// ---------------- helpers -------------------------------------------------------
__device__ __forceinline__ uint32_t smem_u32(const void* p) {
    uint32_t a;
    asm("{ .reg .u64 t; cvta.to.shared.u64 t, %1; cvt.u32.u64 %0, t; }" : "=r"(a) : "l"(p));
    return a;
}

#define MMA_TF32(d, A0, A1, A2, A3, B0, B1)                                       \
    asm volatile("mma.sync.aligned.m16n8k8.row.col.f32.tf32.tf32.f32 "            \
        "{%0,%1,%2,%3},{%4,%5,%6,%7},{%8,%9},{%0,%1,%2,%3};"                      \
        : "+f"((d)[0]), "+f"((d)[1]), "+f"((d)[2]), "+f"((d)[3])                   \
        : "r"(A0), "r"(A1), "r"(A2), "r"(A3), "r"(B0), "r"(B1))

// ======================= tensor-core tf32 GEMM (cp.async, 512 thr) ==============
// C[m,n] = sum_k A[m,k]*B[n,k] + bias[n]
// MODE 0: plain     MODE 1: exact gelu
// MODE 3: out_proj fused LN1:  C = LN(res[m%Nrows] + hasany[m/Nrows]*(acc+bias))
// MODE 4: FFN2 fused LN2:      C = LN(acc + bias + res[m])
// Block tile 128(M) x 256(N); 16 warps, warp tile 64x32; K-chunk 32; 3 stages.
// Smem floats: A stage s @ s*4096 (16KB); B stage s @ 12288 + s*8192 (32KB).
// LN staging buffer (128 x 264) overlaps stages after compute.
#define SMEM_SZ 147456

template <int MODE>
__global__ __launch_bounds__(512, 1) void tgemm(
    const float* __restrict__ A, const float* __restrict__ B,
    const float* __restrict__ bias, const float* __restrict__ res,
    float* __restrict__ C, const float* __restrict__ lg, const float* __restrict__ lb,
    int M, int Nn, int K, int Nrows)
{
    extern __shared__ __align__(128) float sm[];
    uint32_t sbase = smem_u32(sm);
    int tid = threadIdx.x, wid = tid >> 5, lane = tid & 31;
    int m0 = blockIdx.y * 128, n0 = blockIdx.x * 256;
    int wm = wid & 1, wn = wid >> 1;          // warp tile: rows wm*64, cols wn*32
    int nch = K >> 5;

    // ---- async stage loader: A 128x32, B 256x32 floats ----
    auto issue_stage = [&](int c) {
        int k0 = c << 5, buf = c % 3;
        uint32_t sa = sbase + (uint32_t)buf * 16384u;
        uint32_t sb = sbase + 49152u + (uint32_t)buf * 32768u;
#pragma unroll
        for (int j = 0; j < 2; j++) {                 // A: 1024 16B segs
            int seg = tid + j * 512;
            int r = seg >> 3, kk = (seg & 7) << 2;
            uint32_t off = ((uint32_t)(r * 128 + kk * 4)) ^ ((uint32_t)(r & 7) << 4);
            int arow = m0 + r;
            const float* gA = A + (size_t)(arow < M ? arow : M - 1) * K + k0 + kk;
            int szA = (arow < M) ? 16 : 0;
            asm volatile("cp.async.cg.shared.global [%0], [%1], 16, %2;"
                         :: "r"(sa + off), "l"(gA), "r"(szA));
        }
#pragma unroll
        for (int j = 0; j < 4; j++) {                 // B: 2048 16B segs
            int seg = tid + j * 512;
            int r = seg >> 3, kk = (seg & 7) << 2;
            uint32_t off = ((uint32_t)(r * 128 + kk * 4)) ^ ((uint32_t)(r & 7) << 4);
            const float* gB = B + (size_t)(n0 + r) * K + k0 + kk;
            asm volatile("cp.async.cg.shared.global [%0], [%1], 16;"
                         :: "r"(sb + off), "l"(gB));
        }
        asm volatile("cp.async.commit_group;" ::: "memory");
    };

    float acc[16][4] = {};
    int rl = lane >> 2, cc = lane & 3;

    auto compute = [&](int buf) {
        const uint32_t* sa = (const uint32_t*)(sm + buf * 4096);
        const uint32_t* sb = (const uint32_t*)(sm + 12288 + buf * 8192);
#pragma unroll
        for (int ks = 0; ks < 4; ks++) {
            int g0 = (((2 * ks) ^ rl) << 2) + cc;
            int g1 = (((2 * ks + 1) ^ rl) << 2) + cc;
            uint32_t af[4][4];
#pragma unroll
            for (int i = 0; i < 4; i++) {
                int row = wm * 64 + i * 16 + rl;
                af[i][0] = sa[row * 32 + g0];
                af[i][1] = sa[(row + 8) * 32 + g0];
                af[i][2] = sa[row * 32 + g1];
                af[i][3] = sa[(row + 8) * 32 + g1];
            }
            uint32_t bf[4][2];
#pragma unroll
            for (int j = 0; j < 4; j++) {
                int n = wn * 32 + j * 8 + rl;
                bf[j][0] = sb[n * 32 + g0];
                bf[j][1] = sb[n * 32 + g1];
            }
#pragma unroll
            for (int i = 0; i < 4; i++)
#pragma unroll
                for (int j = 0; j < 4; j++)
                    MMA_TF32(acc[i * 4 + j], af[i][0], af[i][1], af[i][2], af[i][3],
                             bf[j][0], bf[j][1]);
        }
    };

    issue_stage(0);
    issue_stage(1);
    for (int c = 0; c < nch; c++) {
        asm volatile("cp.async.wait_group 1;" ::: "memory");
        __syncthreads();
        if (c + 2 < nch) issue_stage(c + 2);
        else asm volatile("cp.async.commit_group;" ::: "memory");
        compute(c % 3);
    }

    int g = lane >> 2, q4 = lane & 3;

    if (MODE == 0 || MODE == 1) {
        // direct epilogue from register accumulators
#pragma unroll
        for (int i = 0; i < 4; i++) {
#pragma unroll
            for (int j = 0; j < 4; j++) {
                int col = n0 + wn * 32 + j * 8 + q4 * 2;
                float b0 = bias[col], b1 = bias[col + 1];
                const float* a4 = acc[i * 4 + j];
#pragma unroll
                for (int half = 0; half < 2; half++) {
                    int mrow = m0 + wm * 64 + i * 16 + g + half * 8;
                    if (mrow >= M) continue;
                    float v0 = a4[half * 2 + 0] + b0;
                    float v1 = a4[half * 2 + 1] + b1;
                    if (MODE == 1) {
                        const float kk = 0.70710678118654752f;
                        v0 = 0.5f * v0 * (1.f + erff(v0 * kk));
                        v1 = 0.5f * v1 * (1.f + erff(v1 * kk));
                    }
                    *(float2*)(C + (size_t)mrow * Nn + col) = make_float2(v0, v1);
                }
            }
        }
    } else {
        // LN-fused epilogue: stage acc+bias into smem (stride 264), then row LN
        asm volatile("cp.async.wait_group 0;" ::: "memory");
        __syncthreads();
        float* sv = sm;
#pragma unroll
        for (int i = 0; i < 4; i++) {
#pragma unroll
            for (int j = 0; j < 4; j++) {
                int col = wn * 32 + j * 8 + q4 * 2;
                float b0 = bias[col], b1 = bias[col + 1];
                const float* a4 = acc[i * 4 + j];
#pragma unroll
                for (int half = 0; half < 2; half++) {
                    int lr = wm * 64 + i * 16 + g + half * 8;
                    sv[lr * 264 + col]     = a4[half * 2 + 0] + b0;
                    sv[lr * 264 + col + 1] = a4[half * 2 + 1] + b1;
                }
            }
        }
        __syncthreads();
        // 16 warps x 8 rows each
        int lr0 = wid * 8;
#pragma unroll
        for (int rr = 0; rr < 8; rr++) {
            int lr = lr0 + rr;
            size_t m = (size_t)m0 + lr;
            float vals[8];
            if (MODE == 3) {
                int b = (int)(m / Nrows), n = (int)(m % Nrows);
                float ha = d_hasany[b] ? 1.f : 0.f;
#pragma unroll
                for (int jj = 0; jj < 8; jj++) {
                    int e = lane + 32 * jj;
                    vals[jj] = res[(size_t)n * 256 + e] + ha * sv[lr * 264 + e];
                }
            } else {
#pragma unroll
                for (int jj = 0; jj < 8; jj++) {
                    int e = lane + 32 * jj;
                    vals[jj] = sv[lr * 264 + e] + res[m * 256 + e];
                }
            }
            float sum = 0.f;
#pragma unroll
            for (int jj = 0; jj < 8; jj++) sum += vals[jj];
#pragma unroll
            for (int o = 16; o; o >>= 1) sum += __shfl_xor_sync(0xffffffffu, sum, o);
            float mu = sum * (1.f / 256.f);
            float s2 = 0.f;
#pragma unroll
            for (int jj = 0; jj < 8; jj++) { float dd = vals[jj] - mu; s2 += dd * dd; }
#pragma unroll
            for (int o = 16; o; o >>= 1) s2 += __shfl_xor_sync(0xffffffffu, s2, o);
            float rs = rsqrtf(s2 * (1.f / 256.f) + 1e-5f);
#pragma unroll
            for (int jj = 0; jj < 8; jj++) {
                int e = lane + 32 * jj;
                C[m * 256 + e] = (vals[jj] - mu) * rs * lg[e] + lb[e];
            }
        }
    }
}

// ---------------- segment scan (batch_assignment is sorted) --------------------
__global__ void seg_kernel(const int* __restrict__ ba, int P, int B) {
    if (threadIdx.x != 0 || blockIdx.x != 0) return;
    for (int b = 0; b < B; b++) {
        int s = P, e = 0;
        for (int p = 0; p < P; p++)
            if (ba[p] == b) { if (p < s) s = p; e = p + 1; }
        if (e > s) { d_segs[2*b] = s; d_segs[2*b+1] = e; d_hasany[b] = 1; }
        else       { d_segs[2*b] = 0; d_segs[2*b+1] = 0; d_hasany[b] = 0; }
    }
}

// ---------------- k/v projection for the 128 gathered rows ---------------------
__global__ void kv_kernel(const float* __restrict__ Hg, const int* __restrict__ idx,
                          const float* __restrict__ ipw, const float* __restrict__ ipb) {
    __shared__ float hrow[Dd];
    int p = blockIdx.x, t = threadIdx.x;
    hrow[t] = Hg[(size_t)idx[p] * Dd + t];
    __syncthreads();
    const float4* h4 = (const float4*)hrow;
    const float4* wk = (const float4*)(ipw + (size_t)(Dd + t) * Dd);
    const float4* wv = (const float4*)(ipw + (size_t)(2 * Dd + t) * Dd);
    float ak = ipb[Dd + t], av = ipb[2 * Dd + t];
#pragma unroll 16
    for (int c = 0; c < Dd / 4; c++) {
        float4 hv = h4[c]; float4 a = wk[c]; float4 b = wv[c];
        ak += hv.x*a.x + hv.y*a.y + hv.z*a.z + hv.w*a.w;
        av += hv.x*b.x + hv.y*b.y + hv.z*b.z + hv.w*b.w;
    }
    d_k[p * Dd + t] = ak;
    d_v[p * Dd + t] = av;
}

// ---------------- per-head scores: scale * q_h @ k_h^T -------------------------
// K cached in 32 regs (conflict-free 33-stride), q via broadcast LDS.128
__global__ void scores_kernel(int N) {
    int h = blockIdx.y;
    int n0 = blockIdx.x * 64;
    __shared__ float ks[128 * 33];
    __shared__ float qs[64 * 32];
    int tid = threadIdx.x;
    for (int i = tid; i < 128 * 32; i += 256) {
        int p = i >> 5, e = i & 31;
        ks[p * 33 + e] = d_k[p * Dd + h * DHh + e];
    }
    for (int i = tid; i < 64 * 32; i += 256) {
        int r = i >> 5, e = i & 31;
        int n = n0 + r;
        qs[i] = (n < N) ? d_q[(size_t)n * Dd + h * DHh + e] : 0.f;
    }
    __syncthreads();
    int tp = tid & 127, half = tid >> 7;
    float kreg[32];
#pragma unroll
    for (int e = 0; e < 32; e++) kreg[e] = ks[tp * 33 + e];
    const float scale = 0.17677669529663687f;  // 1/sqrt(32)
#pragma unroll 4
    for (int rr = 0; rr < 32; rr++) {
        int r = half * 32 + rr;
        int n = n0 + r;
        if (n >= N) break;
        const float4* q4 = (const float4*)(qs + r * 32);
        float s = 0.f;
#pragma unroll
        for (int c = 0; c < 8; c++) {
            float4 qv = q4[c];
            s += qv.x * kreg[c*4] + qv.y * kreg[c*4+1] + qv.z * kreg[c*4+2] + qv.w * kreg[c*4+3];
        }
        d_scores[((size_t)n * Hh + h) * Pmax + tp] = s * scale;
    }
}

// ---------------- segment softmax + ctx accumulation ---------------------------
__global__ void attn_kernel(int N) {
    int b = blockIdx.y;
    int h = threadIdx.x >> 5, l = threadIdx.x & 31;
    int s = d_segs[2 * b], e = d_segs[2 * b + 1];
    int L = e - s;
    __shared__ float ws[8][128];
    int nEnd = min(N, (int)(blockIdx.x + 1) * 16);
    for (int n = blockIdx.x * 16; n < nEnd; n++) {
        size_t obase = ((size_t)b * N + n) * Dd + h * DHh;
        if (L <= 0) { d_ctx[obase + l] = 0.f; continue; }
        float sc[4]; int cnt = 0;
        float m = -1e30f;
        for (int pl = l; pl < L; pl += 32) {
            float xv = d_scores[((size_t)n * Hh + h) * Pmax + s + pl];
            sc[cnt++] = xv;
            m = fmaxf(m, xv);
        }
#pragma unroll
        for (int o = 16; o; o >>= 1) m = fmaxf(m, __shfl_xor_sync(0xffffffffu, m, o));
        float sum = 0.f; cnt = 0;
        for (int pl = l; pl < L; pl += 32) {
            float w = __expf(sc[cnt++] - m);
            ws[h][pl] = w;
            sum += w;
        }
#pragma unroll
        for (int o = 16; o; o >>= 1) sum += __shfl_xor_sync(0xffffffffu, sum, o);
        float inv = 1.f / sum;
        __syncwarp();
        float acc = 0.f;
        for (int pl = 0; pl < L; pl++)
            acc += ws[h][pl] * d_v[(size_t)(s + pl) * Dd + h * DHh + l];
        d_ctx[obase + l] = acc * inv;
        __syncwarp();
    }
}

// -------------------------------- launch ---------------------------------------
extern "C" void kernel_launch(void* const* d_in, const int* in_sizes, int n_in,
                              void* d_out, int out_size) {
    const float* Hg  = (const float*)d_in[0];
    const int*  pidx = (const int*)d_in[1];
    const int*  ba   = (const int*)d_in[2];
    const float* ipw = (const float*)d_in[4];
    const float* ipb = (const float*)d_in[5];
    const float* opw = (const float*)d_in[6];
    const float* opb = (const float*)d_in[7];
    const float* w1  = (const float*)d_in[8];
    const float* b1  = (const float*)d_in[9];
    const float* w2  = (const float*)d_in[10];
    const float* b2  = (const float*)d_in[11];
    const float* g1  = (const float*)d_in[12];
    const float* be1 = (const float*)d_in[13];
    const float* g2  = (const float*)d_in[14];
    const float* be2 = (const float*)d_in[15];
    float* out = (float*)d_out;

    int N = in_sizes[0] / Dd;          // 6000
    int P = in_sizes[1];               // 128
    int B = out_size / (N * Dd);       // 16
    int M = B * N;                     // 96000

    float *q, *ctx, *x, *hidden;
    cudaGetSymbolAddress((void**)&q,      d_q);
    cudaGetSymbolAddress((void**)&ctx,    d_ctx);
    cudaGetSymbolAddress((void**)&x,      d_x);
    cudaGetSymbolAddress((void**)&hidden, d_hidden);

    cudaFuncSetAttribute(tgemm<0>, cudaFuncAttributeMaxDynamicSharedMemorySize, SMEM_SZ);
    cudaFuncSetAttribute(tgemm<1>, cudaFuncAttributeMaxDynamicSharedMemorySize, SMEM_SZ);
    cudaFuncSetAttribute(tgemm<3>, cudaFuncAttributeMaxDynamicSharedMemorySize, SMEM_SZ);
    cudaFuncSetAttribute(tgemm<4>, cudaFuncAttributeMaxDynamicSharedMemorySize, SMEM_SZ);

    // 1. batch segments
    seg_kernel<<<1, 1>>>(ba, P, B);
    // 2. k/v projections of gathered rows
    kv_kernel<<<P, Dd>>>(Hg, pidx, ipw, ipb);
    // 3. q = H @ Wq^T + bq
    tgemm<0><<<dim3(1, (N + 127) / 128), 512, SMEM_SZ>>>(
        Hg, ipw, ipb, nullptr, q, nullptr, nullptr, N, Dd, Dd, N);
    // 4. per-head scores
    scores_kernel<<<dim3((N + 63) / 64, Hh), 256>>>(N);
    // 5. segment softmax + ctx
    attn_kernel<<<dim3((N + 15) / 16, B), 256>>>(N);
    // 6. x = LN1(H + has_any*(ctx @ Wout^T + bout))   [fused epilogue]
    tgemm<3><<<dim3(1, M / 128), 512, SMEM_SZ>>>(
        ctx, opw, opb, Hg, x, g1, be1, M, Dd, Dd, N);
    // 7. hidden = gelu(x @ W1^T + b1)
    tgemm<1><<<dim3(FF / 256, M / 128), 512, SMEM_SZ>>>(
        x, w1, b1, nullptr, hidden, nullptr, nullptr, M, FF, Dd, N);
    // 8. out = LN2(x + hidden @ W2^T + b2)            [fused epilogue]
    tgemm<4><<<dim3(1, M / 128), 512, SMEM_SZ>>>(
        hidden, w2, b2, x, out, g2, be2, M, Dd, FF, N);
}

// round 6
// speedup vs baseline: 4.6648x; 1.3870x over previous
#include <cuda_runtime.h>
#include <cuda_fp16.h>
#include <math.h>
#include <stdint.h>

// Problem constants
#define Dd 256
#define Hh 8
#define DHh 32
#define Pmax 128
#define Bmax 16
#define Nmax 6000
#define FF 1024

// ---------------- scratch (static __device__ — no allocation allowed) ----------
__device__ float  d_q[Nmax * Dd];
__device__ float  d_k[Pmax * Dd];
__device__ float  d_v[Pmax * Dd];
__device__ float  d_scores[(size_t)Nmax * Hh * Pmax];
__device__ float  d_x[(size_t)Bmax * Nmax * Dd];        // post-LN1 (fp32, residual)
__device__ __half d_x16[(size_t)Bmax * Nmax * Dd];      // post-LN1 (fp16, GEMM A)
__device__ __half d_ctx16[(size_t)Bmax * Nmax * Dd];    // attention context fp16
__device__ __half d_hidden16[(size_t)Bmax * Nmax * FF]; // FFN hidden fp16
__device__ __half d_hg16[Nmax * Dd];                    // H_genes fp16
__device__ __half d_wq16[Dd * Dd];
__device__ __half d_wo16[Dd * Dd];
__device__ __half d_w116[FF * Dd];
__device__ __half d_w216[Dd * FF];
__device__ int    d_segs[2 * Bmax];
__device__ int    d_hasany[Bmax];

// ---------------- helpers -------------------------------------------------------
__device__ __forceinline__ uint32_t smem_u32(const void* p) {
    uint32_t a;
    asm("{ .reg .u64 t; cvta.to.shared.u64 t, %1; cvt.u32.u64 %0, t; }" : "=r"(a) : "l"(p));
    return a;
}

#define LDSM4(R0, R1, R2, R3, ADDR)                                               \
    asm volatile("ldmatrix.sync.aligned.m8n8.x4.shared.b16 {%0,%1,%2,%3}, [%4];"  \
        : "=r"(R0), "=r"(R1), "=r"(R2), "=r"(R3) : "r"(ADDR))

#define MMA_F16(d, A0, A1, A2, A3, B0, B1)                                        \
    asm volatile("mma.sync.aligned.m16n8k16.row.col.f32.f16.f16.f32 "             \
        "{%0,%1,%2,%3},{%4,%5,%6,%7},{%8,%9},{%0,%1,%2,%3};"                      \
        : "+f"((d)[0]), "+f"((d)[1]), "+f"((d)[2]), "+f"((d)[3])                   \
        : "r"(A0), "r"(A1), "r"(A2), "r"(A3), "r"(B0), "r"(B1))

// ---------------- fp32 -> fp16 conversion ---------------------------------------
__global__ void f2h_kernel(const float* __restrict__ src, __half* __restrict__ dst, int n) {
    int i = (blockIdx.x * blockDim.x + threadIdx.x) * 4;
    if (i < n) {
        float4 v = *(const float4*)(src + i);
        __half2* d2 = (__half2*)(dst + i);
        d2[0] = __floats2half2_rn(v.x, v.y);
        d2[1] = __floats2half2_rn(v.z, v.w);
    }
}

// ======================= fp16 tensor-core GEMM (cp.async + ldmatrix) ============
// C[m,n] = sum_k A[m,k]*B[n,k] + bias[n]   (A, B fp16; accum fp32)
// MODE 0: C fp32              MODE 1: gelu -> C16 fp16
// MODE 3: LN1 fused: v = res[m%Nrows] + hasany*(acc+bias); LN -> C fp32 + C16
// MODE 4: LN2 fused: v = acc + bias + res[m]; LN -> C fp32
// Block tile 128(M) x 256(N); 16 warps, warp 64x32; K-chunk 64 fp16; 3 stages.
// Smem: A stage s @ s*16KB; B stage s @ 48KB + s*32KB. 128B rows, XOR swizzle.
#define SMEM_SZ 147456

template <int MODE>
__global__ __launch_bounds__(512, 1) void tgemm(
    const __half* __restrict__ A, const __half* __restrict__ B,
    const float* __restrict__ bias, const float* __restrict__ res,
    float* __restrict__ C, __half* __restrict__ C16,
    const float* __restrict__ lg, const float* __restrict__ lb,
    int M, int Nn, int K, int Nrows)
{
    extern __shared__ __align__(128) float sm[];
    uint32_t sbase = smem_u32(sm);
    int tid = threadIdx.x, wid = tid >> 5, lane = tid & 31;
    int m0 = blockIdx.y * 128, n0 = blockIdx.x * 256;
    int wm = wid & 1, wn = wid >> 1;          // warp tile: rows wm*64, cols wn*32
    int nch = K >> 6;                          // 64 fp16 per chunk

    // ---- async stage loader: A 128x64, B 256x64 halfs (128B rows) ----
    auto issue_stage = [&](int c) {
        int k0 = c << 6, buf = c % 3;
        uint32_t sa = sbase + (uint32_t)buf * 16384u;
        uint32_t sb = sbase + 49152u + (uint32_t)buf * 32768u;
#pragma unroll
        for (int j = 0; j < 2; j++) {                 // A: 1024 16B segs
            int seg = tid + j * 512;
            int r = seg >> 3, kk = (seg & 7) << 3;    // fp16 col
            uint32_t off = ((uint32_t)(r * 128 + kk * 2)) ^ ((uint32_t)(r & 7) << 4);
            int arow = m0 + r;
            const __half* gA = A + (size_t)(arow < M ? arow : M - 1) * K + k0 + kk;
            int szA = (arow < M) ? 16 : 0;
            asm volatile("cp.async.cg.shared.global [%0], [%1], 16, %2;"
                         :: "r"(sa + off), "l"(gA), "r"(szA));
        }
#pragma unroll
        for (int j = 0; j < 4; j++) {                 // B: 2048 16B segs
            int seg = tid + j * 512;
            int r = seg >> 3, kk = (seg & 7) << 3;
            uint32_t off = ((uint32_t)(r * 128 + kk * 2)) ^ ((uint32_t)(r & 7) << 4);
            const __half* gB = B + (size_t)(n0 + r) * K + k0 + kk;
            asm volatile("cp.async.cg.shared.global [%0], [%1], 16;"
                         :: "r"(sb + off), "l"(gB));
        }
        asm volatile("cp.async.commit_group;" ::: "memory");
    };

    float acc[16][4] = {};

    // ldmatrix source coordinates (per thread)
    int a_mloc = lane & 15;                    // row within m16 tile
    int a_kb   = (lane >> 4) << 4;             // 0 or 16 bytes
    int b_nloc = (((lane >> 4) & 1) << 3) + (lane & 7);  // row within n16 pair
    int b_kb   = ((lane >> 3) & 1) << 4;

    auto compute = [&](int buf) {
        uint32_t sa = sbase + (uint32_t)buf * 16384u;
        uint32_t sb = sbase + 49152u + (uint32_t)buf * 32768u;
#pragma unroll
        for (int ks = 0; ks < 4; ks++) {
            int kb = ks * 32;
            uint32_t af[4][4];
#pragma unroll
            for (int i = 0; i < 4; i++) {
                int row = wm * 64 + i * 16 + a_mloc;
                uint32_t off = ((uint32_t)(row * 128 + kb + a_kb)) ^ ((uint32_t)(row & 7) << 4);
                LDSM4(af[i][0], af[i][1], af[i][2], af[i][3], sa + off);
            }
            uint32_t bf[4][2];
#pragma unroll
            for (int jj = 0; jj < 2; jj++) {
                int row = wn * 32 + jj * 16 + b_nloc;
                uint32_t off = ((uint32_t)(row * 128 + kb + b_kb)) ^ ((uint32_t)(row & 7) << 4);
                uint32_t r0, r1, r2, r3;
                LDSM4(r0, r1, r2, r3, sb + off);
                bf[jj * 2][0] = r0; bf[jj * 2][1] = r1;
                bf[jj * 2 + 1][0] = r2; bf[jj * 2 + 1][1] = r3;
            }
#pragma unroll
            for (int i = 0; i < 4; i++)
#pragma unroll
                for (int j = 0; j < 4; j++)
                    MMA_F16(acc[i * 4 + j], af[i][0], af[i][1], af[i][2], af[i][3],
                            bf[j][0], bf[j][1]);
        }
    };

    issue_stage(0);
    if (nch > 1) issue_stage(1);
    else asm volatile("cp.async.commit_group;" ::: "memory");
    for (int c = 0; c < nch; c++) {
        asm volatile("cp.async.wait_group 1;" ::: "memory");
        __syncthreads();
        if (c + 2 < nch) issue_stage(c + 2);
        else asm volatile("cp.async.commit_group;" ::: "memory");
        compute(c % 3);
    }

    int g = lane >> 2, q4 = lane & 3;

    if (MODE == 0 || MODE == 1) {
#pragma unroll
        for (int i = 0; i < 4; i++) {
#pragma unroll
            for (int j = 0; j < 4; j++) {
                int col = n0 + wn * 32 + j * 8 + q4 * 2;
                float b0 = bias[col], b1 = bias[col + 1];
                const float* a4 = acc[i * 4 + j];
#pragma unroll
                for (int half = 0; half < 2; half++) {
                    int mrow = m0 + wm * 64 + i * 16 + g + half * 8;
                    if (mrow >= M) continue;
                    float v0 = a4[half * 2 + 0] + b0;
                    float v1 = a4[half * 2 + 1] + b1;
                    if (MODE == 1) {
                        const float kk = 0.70710678118654752f;
                        v0 = 0.5f * v0 * (1.f + erff(v0 * kk));
                        v1 = 0.5f * v1 * (1.f + erff(v1 * kk));
                        *(__half2*)(C16 + (size_t)mrow * Nn + col) = __floats2half2_rn(v0, v1);
                    } else {
                        *(float2*)(C + (size_t)mrow * Nn + col) = make_float2(v0, v1);
                    }
                }
            }
        }
    } else {
        // LN-fused epilogue: stage acc+bias into smem (stride 264), then row LN
        asm volatile("cp.async.wait_group 0;" ::: "memory");
        __syncthreads();
        float* sv = sm;
#pragma unroll
        for (int i = 0; i < 4; i++) {
#pragma unroll
            for (int j = 0; j < 4; j++) {
                int col = wn * 32 + j * 8 + q4 * 2;
                float b0 = bias[col], b1 = bias[col + 1];
                const float* a4 = acc[i * 4 + j];
#pragma unroll
                for (int half = 0; half < 2; half++) {
                    int lr = wm * 64 + i * 16 + g + half * 8;
                    sv[lr * 264 + col]     = a4[half * 2 + 0] + b0;
                    sv[lr * 264 + col + 1] = a4[half * 2 + 1] + b1;
                }
            }
        }
        __syncthreads();
        int lr0 = wid * 8;
#pragma unroll
        for (int rr = 0; rr < 8; rr++) {
            int lr = lr0 + rr;
            size_t m = (size_t)m0 + lr;
            float vals[8];
            if (MODE == 3) {
                int b = (int)(m / Nrows), n = (int)(m % Nrows);
                float ha = d_hasany[b] ? 1.f : 0.f;
#pragma unroll
                for (int jj = 0; jj < 8; jj++) {
                    int e = lane + 32 * jj;
                    vals[jj] = res[(size_t)n * 256 + e] + ha * sv[lr * 264 + e];
                }
            } else {
#pragma unroll
                for (int jj = 0; jj < 8; jj++) {
                    int e = lane + 32 * jj;
                    vals[jj] = sv[lr * 264 + e] + res[m * 256 + e];
                }
            }
            float sum = 0.f;
#pragma unroll
            for (int jj = 0; jj < 8; jj++) sum += vals[jj];
#pragma unroll
            for (int o = 16; o; o >>= 1) sum += __shfl_xor_sync(0xffffffffu, sum, o);
            float mu = sum * (1.f / 256.f);
            float s2 = 0.f;
#pragma unroll
            for (int jj = 0; jj < 8; jj++) { float dd = vals[jj] - mu; s2 += dd * dd; }
#pragma unroll
            for (int o = 16; o; o >>= 1) s2 += __shfl_xor_sync(0xffffffffu, s2, o);
            float rs = rsqrtf(s2 * (1.f / 256.f) + 1e-5f);
#pragma unroll
            for (int jj = 0; jj < 8; jj++) {
                int e = lane + 32 * jj;
                float ov = (vals[jj] - mu) * rs * lg[e] + lb[e];
                C[m * 256 + e] = ov;
                if (MODE == 3) C16[m * 256 + e] = __float2half(ov);
            }
        }
    }
}

// ---------------- segment scan (batch_assignment is sorted) --------------------
__global__ void seg_kernel(const int* __restrict__ ba, int P, int B) {
    if (threadIdx.x != 0 || blockIdx.x != 0) return;
    for (int b = 0; b < B; b++) {
        int s = P, e = 0;
        for (int p = 0; p < P; p++)
            if (ba[p] == b) { if (p < s) s = p; e = p + 1; }
        if (e > s) { d_segs[2*b] = s; d_segs[2*b+1] = e; d_hasany[b] = 1; }
        else       { d_segs[2*b] = 0; d_segs[2*b+1] = 0; d_hasany[b] = 0; }
    }
}

// ---------------- k/v projection for the 128 gathered rows ---------------------
__global__ void kv_kernel(const float* __restrict__ Hg, const int* __restrict__ idx,
                          const float* __restrict__ ipw, const float* __restrict__ ipb) {
    __shared__ float hrow[Dd];
    int p = blockIdx.x, t = threadIdx.x;
    hrow[t] = Hg[(size_t)idx[p] * Dd + t];
    __syncthreads();
    const float4* h4 = (const float4*)hrow;
    const float4* wk = (const float4*)(ipw + (size_t)(Dd + t) * Dd);
    const float4* wv = (const float4*)(ipw + (size_t)(2 * Dd + t) * Dd);
    float ak = ipb[Dd + t], av = ipb[2 * Dd + t];
#pragma unroll 16
    for (int c = 0; c < Dd / 4; c++) {
        float4 hv = h4[c]; float4 a = wk[c]; float4 b = wv[c];
        ak += hv.x*a.x + hv.y*a.y + hv.z*a.z + hv.w*a.w;
        av += hv.x*b.x + hv.y*b.y + hv.z*b.z + hv.w*b.w;
    }
    d_k[p * Dd + t] = ak;
    d_v[p * Dd + t] = av;
}

// ---------------- per-head scores: scale * q_h @ k_h^T -------------------------
__global__ void scores_kernel(int N) {
    int h = blockIdx.y;
    int n0 = blockIdx.x * 64;
    __shared__ float ks[128 * 33];
    __shared__ float qs[64 * 32];
    int tid = threadIdx.x;
    for (int i = tid; i < 128 * 32; i += 256) {
        int p = i >> 5, e = i & 31;
        ks[p * 33 + e] = d_k[p * Dd + h * DHh + e];
    }
    for (int i = tid; i < 64 * 32; i += 256) {
        int r = i >> 5, e = i & 31;
        int n = n0 + r;
        qs[i] = (n < N) ? d_q[(size_t)n * Dd + h * DHh + e] : 0.f;
    }
    __syncthreads();
    int tp = tid & 127, half = tid >> 7;
    float kreg[32];
#pragma unroll
    for (int e = 0; e < 32; e++) kreg[e] = ks[tp * 33 + e];
    const float scale = 0.17677669529663687f;  // 1/sqrt(32)
#pragma unroll 4
    for (int rr = 0; rr < 32; rr++) {
        int r = half * 32 + rr;
        int n = n0 + r;
        if (n >= N) break;
        const float4* q4 = (const float4*)(qs + r * 32);
        float s = 0.f;
#pragma unroll
        for (int c = 0; c < 8; c++) {
            float4 qv = q4[c];
            s += qv.x * kreg[c*4] + qv.y * kreg[c*4+1] + qv.z * kreg[c*4+2] + qv.w * kreg[c*4+3];
        }
        d_scores[((size_t)n * Hh + h) * Pmax + tp] = s * scale;
    }
}

// ---------------- segment softmax + ctx accumulation (fp16 out) ----------------
__global__ void attn_kernel(int N) {
    int b = blockIdx.y;
    int h = threadIdx.x >> 5, l = threadIdx.x & 31;
    int s = d_segs[2 * b], e = d_segs[2 * b + 1];
    int L = e - s;
    __shared__ float ws[8][128];
    int nEnd = min(N, (int)(blockIdx.x + 1) * 16);
    for (int n = blockIdx.x * 16; n < nEnd; n++) {
        size_t obase = ((size_t)b * N + n) * Dd + h * DHh;
        if (L <= 0) { d_ctx16[obase + l] = __float2half(0.f); continue; }
        float sc[4]; int cnt = 0;
        float m = -1e30f;
        for (int pl = l; pl < L; pl += 32) {
            float xv = d_scores[((size_t)n * Hh + h) * Pmax + s + pl];
            sc[cnt++] = xv;
            m = fmaxf(m, xv);
        }
#pragma unroll
        for (int o = 16; o; o >>= 1) m = fmaxf(m, __shfl_xor_sync(0xffffffffu, m, o));
        float sum = 0.f; cnt = 0;
        for (int pl = l; pl < L; pl += 32) {
            float w = __expf(sc[cnt++] - m);
            ws[h][pl] = w;
            sum += w;
        }
#pragma unroll
        for (int o = 16; o; o >>= 1) sum += __shfl_xor_sync(0xffffffffu, sum, o);
        float inv = 1.f / sum;
        __syncwarp();
        float acc = 0.f;
        for (int pl = 0; pl < L; pl++)
            acc += ws[h][pl] * d_v[(size_t)(s + pl) * Dd + h * DHh + l];
        d_ctx16[obase + l] = __float2half(acc * inv);
        __syncwarp();
    }
}

// -------------------------------- launch ---------------------------------------
extern "C" void kernel_launch(void* const* d_in, const int* in_sizes, int n_in,
                              void* d_out, int out_size) {
    const float* Hg  = (const float*)d_in[0];
    const int*  pidx = (const int*)d_in[1];
    const int*  ba   = (const int*)d_in[2];
    const float* ipw = (const float*)d_in[4];
    const float* ipb = (const float*)d_in[5];
    const float* opw = (const float*)d_in[6];
    const float* opb = (const float*)d_in[7];
    const float* w1  = (const float*)d_in[8];
    const float* b1  = (const float*)d_in[9];
    const float* w2  = (const float*)d_in[10];
    const float* b2  = (const float*)d_in[11];
    const float* g1  = (const float*)d_in[12];
    const float* be1 = (const float*)d_in[13];
    const float* g2  = (const float*)d_in[14];
    const float* be2 = (const float*)d_in[15];
    float* out = (float*)d_out;

    int N = in_sizes[0] / Dd;          // 6000
    int P = in_sizes[1];               // 128
    int B = out_size / (N * Dd);       // 16
    int M = B * N;                     // 96000

    float *q, *x;
    __half *hg16, *wq16, *wo16, *w116, *w216, *x16, *ctx16, *hidden16;
    cudaGetSymbolAddress((void**)&q,        d_q);
    cudaGetSymbolAddress((void**)&x,        d_x);
    cudaGetSymbolAddress((void**)&hg16,     d_hg16);
    cudaGetSymbolAddress((void**)&wq16,     d_wq16);
    cudaGetSymbolAddress((void**)&wo16,     d_wo16);
    cudaGetSymbolAddress((void**)&w116,     d_w116);
    cudaGetSymbolAddress((void**)&w216,     d_w216);
    cudaGetSymbolAddress((void**)&x16,      d_x16);
    cudaGetSymbolAddress((void**)&ctx16,    d_ctx16);
    cudaGetSymbolAddress((void**)&hidden16, d_hidden16);

    cudaFuncSetAttribute(tgemm<0>, cudaFuncAttributeMaxDynamicSharedMemorySize, SMEM_SZ);
    cudaFuncSetAttribute(tgemm<1>, cudaFuncAttributeMaxDynamicSharedMemorySize, SMEM_SZ);
    cudaFuncSetAttribute(tgemm<3>, cudaFuncAttributeMaxDynamicSharedMemorySize, SMEM_SZ);
    cudaFuncSetAttribute(tgemm<4>, cudaFuncAttributeMaxDynamicSharedMemorySize, SMEM_SZ);

    // 0. fp16 conversions (weights + H_genes)
    f2h_kernel<<<(N * Dd / 4 + 255) / 256, 256>>>(Hg, hg16, N * Dd);
    f2h_kernel<<<(Dd * Dd / 4 + 255) / 256, 256>>>(ipw, wq16, Dd * Dd);
    f2h_kernel<<<(Dd * Dd / 4 + 255) / 256, 256>>>(opw, wo16, Dd * Dd);
    f2h_kernel<<<(FF * Dd / 4 + 255) / 256, 256>>>(w1, w116, FF * Dd);
    f2h_kernel<<<(Dd * FF / 4 + 255) / 256, 256>>>(w2, w216, Dd * FF);
    // 1. batch segments
    seg_kernel<<<1, 1>>>(ba, P, B);
    // 2. k/v projections of gathered rows (fp32)
    kv_kernel<<<P, Dd>>>(Hg, pidx, ipw, ipb);
    // 3. q = H @ Wq^T + bq  (fp16 mma -> fp32 out)
    tgemm<0><<<dim3(1, (N + 127) / 128), 512, SMEM_SZ>>>(
        hg16, wq16, ipb, nullptr, q, nullptr, nullptr, nullptr, N, Dd, Dd, N);
    // 4. per-head scores
    scores_kernel<<<dim3((N + 63) / 64, Hh), 256>>>(N);
    // 5. segment softmax + ctx (fp16 out)
    attn_kernel<<<dim3((N + 15) / 16, B), 256>>>(N);
    // 6. x = LN1(H + has_any*(ctx @ Wout^T + bout))  -> fp32 + fp16
    tgemm<3><<<dim3(1, M / 128), 512, SMEM_SZ>>>(
        ctx16, wo16, opb, Hg, x, x16, g1, be1, M, Dd, Dd, N);
    // 7. hidden = gelu(x @ W1^T + b1) -> fp16
    tgemm<1><<<dim3(FF / 256, M / 128), 512, SMEM_SZ>>>(
        x16, w116, b1, nullptr, nullptr, hidden16, nullptr, nullptr, M, FF, Dd, N);
    // 8. out = LN2(x + hidden @ W2^T + b2)
    tgemm<4><<<dim3(1, M / 128), 512, SMEM_SZ>>>(
        hidden16, w216, b2, x, out, nullptr, g2, be2, M, Dd, FF, N);
}

// round 7
// speedup vs baseline: 5.0640x; 1.0856x over previous
#include <cuda_runtime.h>
#include <cuda_fp16.h>
#include <math.h>
#include <stdint.h>

// Problem constants
#define Dd 256
#define Hh 8
#define DHh 32
#define Pmax 128
#define Bmax 16
#define Nmax 6000
#define FF 1024

// ---------------- scratch (static __device__ — no allocation allowed) ----------
__device__ float  d_q[Nmax * Dd];
__device__ float  d_k[Pmax * Dd];
__device__ float  d_v[Pmax * Dd];
__device__ float  d_scores[(size_t)Nmax * Hh * Pmax];
__device__ float  d_x[(size_t)Bmax * Nmax * Dd];        // post-LN1 (fp32, residual)
__device__ __half d_x16[(size_t)Bmax * Nmax * Dd];      // post-LN1 (fp16, GEMM A)
__device__ __half d_ctx16[(size_t)Bmax * Nmax * Dd];    // attention context fp16
__device__ __half d_hidden16[(size_t)Bmax * Nmax * FF]; // FFN hidden fp16
__device__ __half d_hg16[Nmax * Dd];                    // H_genes fp16
__device__ __half d_wq16[Dd * Dd];
__device__ __half d_wo16[Dd * Dd];
__device__ __half d_w116[FF * Dd];
__device__ __half d_w216[Dd * FF];
__device__ int    d_segs[2 * Bmax];
__device__ int    d_hasany[Bmax];

// ---------------- helpers -------------------------------------------------------
__device__ __forceinline__ uint32_t smem_u32(const void* p) {
    uint32_t a;
    asm("{ .reg .u64 t; cvta.to.shared.u64 t, %1; cvt.u32.u64 %0, t; }" : "=r"(a) : "l"(p));
    return a;
}

// fast GELU: 0.5x(1+tanh(sqrt(2/pi)(x + 0.044715 x^3))), tanh.approx MUFU
__device__ __forceinline__ float fast_gelu(float x) {
    float x2 = x * x;
    float u = x * fmaf(0.0356774081f, x2, 0.7978845608f);
    float t;
    asm("tanh.approx.f32 %0, %1;" : "=f"(t) : "f"(u));
    float hx = 0.5f * x;
    return fmaf(hx, t, hx);
}

#define LDSM4(R0, R1, R2, R3, ADDR)                                               \
    asm volatile("ldmatrix.sync.aligned.m8n8.x4.shared.b16 {%0,%1,%2,%3}, [%4];"  \
        : "=r"(R0), "=r"(R1), "=r"(R2), "=r"(R3) : "r"(ADDR))

#define MMA_F16(d, A0, A1, A2, A3, B0, B1)                                        \
    asm volatile("mma.sync.aligned.m16n8k16.row.col.f32.f16.f16.f32 "             \
        "{%0,%1,%2,%3},{%4,%5,%6,%7},{%8,%9},{%0,%1,%2,%3};"                      \
        : "+f"((d)[0]), "+f"((d)[1]), "+f"((d)[2]), "+f"((d)[3])                   \
        : "r"(A0), "r"(A1), "r"(A2), "r"(A3), "r"(B0), "r"(B1))

// ---------------- single fused fp32 -> fp16 conversion ---------------------------
// segments (in float4 units): hg 384000 | wq 16384 | wo 16384 | w1 65536 | w2 65536
#define HG4 (Nmax * Dd / 4)
#define WQ4 (Dd * Dd / 4)
#define W14 (FF * Dd / 4)
__global__ void f2h_all(const float* __restrict__ Hg, const float* __restrict__ ipw,
                        const float* __restrict__ opw, const float* __restrict__ w1,
                        const float* __restrict__ w2) {
    int i = blockIdx.x * blockDim.x + threadIdx.x;
    const float* src; __half* dst; int off;
    if (i < HG4)                       { src = Hg;  dst = d_hg16; off = i; }
    else if (i < HG4 + WQ4)            { src = ipw; dst = d_wq16; off = i - HG4; }
    else if (i < HG4 + 2*WQ4)          { src = opw; dst = d_wo16; off = i - HG4 - WQ4; }
    else if (i < HG4 + 2*WQ4 + W14)    { src = w1;  dst = d_w116; off = i - HG4 - 2*WQ4; }
    else if (i < HG4 + 2*WQ4 + 2*W14)  { src = w2;  dst = d_w216; off = i - HG4 - 2*WQ4 - W14; }
    else return;
    float4 v = *(const float4*)(src + off * 4);
    __half2* d2 = (__half2*)(dst + off * 4);
    d2[0] = __floats2half2_rn(v.x, v.y);
    d2[1] = __floats2half2_rn(v.z, v.w);
}

// ======================= fp16 tensor-core GEMM (cp.async + ldmatrix) ============
// C[m,n] = sum_k A[m,k]*B[n,k] + bias[n]   (A, B fp16; accum fp32)
// MODE 0: C fp32              MODE 1: fast gelu -> C16 fp16
// MODE 3: LN1 fused: v = res[m%Nrows] + hasany*(acc+bias); LN -> C fp32 + C16
// MODE 4: LN2 fused: v = acc + bias + res[m]; LN -> C fp32
// Block tile 128(M) x 256(N); 16 warps, warp 64x32; K-chunk 64 fp16; 3 stages.
#define SMEM_SZ 147456

template <int MODE>
__global__ __launch_bounds__(512, 1) void tgemm(
    const __half* __restrict__ A, const __half* __restrict__ B,
    const float* __restrict__ bias, const float* __restrict__ res,
    float* __restrict__ C, __half* __restrict__ C16,
    const float* __restrict__ lg, const float* __restrict__ lb,
    int M, int Nn, int K, int Nrows)
{
    extern __shared__ __align__(128) float sm[];
    uint32_t sbase = smem_u32(sm);
    int tid = threadIdx.x, wid = tid >> 5, lane = tid & 31;
    int m0 = blockIdx.y * 128, n0 = blockIdx.x * 256;
    int wm = wid & 1, wn = wid >> 1;
    int nch = K >> 6;

    auto issue_stage = [&](int c) {
        int k0 = c << 6, buf = c % 3;
        uint32_t sa = sbase + (uint32_t)buf * 16384u;
        uint32_t sb = sbase + 49152u + (uint32_t)buf * 32768u;
#pragma unroll
        for (int j = 0; j < 2; j++) {
            int seg = tid + j * 512;
            int r = seg >> 3, kk = (seg & 7) << 3;
            uint32_t off = ((uint32_t)(r * 128 + kk * 2)) ^ ((uint32_t)(r & 7) << 4);
            int arow = m0 + r;
            const __half* gA = A + (size_t)(arow < M ? arow : M - 1) * K + k0 + kk;
            int szA = (arow < M) ? 16 : 0;
            asm volatile("cp.async.cg.shared.global [%0], [%1], 16, %2;"
                         :: "r"(sa + off), "l"(gA), "r"(szA));
        }
#pragma unroll
        for (int j = 0; j < 4; j++) {
            int seg = tid + j * 512;
            int r = seg >> 3, kk = (seg & 7) << 3;
            uint32_t off = ((uint32_t)(r * 128 + kk * 2)) ^ ((uint32_t)(r & 7) << 4);
            const __half* gB = B + (size_t)(n0 + r) * K + k0 + kk;
            asm volatile("cp.async.cg.shared.global [%0], [%1], 16;"
                         :: "r"(sb + off), "l"(gB));
        }
        asm volatile("cp.async.commit_group;" ::: "memory");
    };

    float acc[16][4] = {};

    int a_mloc = lane & 15;
    int a_kb   = (lane >> 4) << 4;
    int b_nloc = (((lane >> 4) & 1) << 3) + (lane & 7);
    int b_kb   = ((lane >> 3) & 1) << 4;

    auto compute = [&](int buf) {
        uint32_t sa = sbase + (uint32_t)buf * 16384u;
        uint32_t sb = sbase + 49152u + (uint32_t)buf * 32768u;
#pragma unroll
        for (int ks = 0; ks < 4; ks++) {
            int kb = ks * 32;
            uint32_t af[4][4];
#pragma unroll
            for (int i = 0; i < 4; i++) {
                int row = wm * 64 + i * 16 + a_mloc;
                uint32_t off = ((uint32_t)(row * 128 + kb + a_kb)) ^ ((uint32_t)(row & 7) << 4);
                LDSM4(af[i][0], af[i][1], af[i][2], af[i][3], sa + off);
            }
            uint32_t bf[4][2];
#pragma unroll
            for (int jj = 0; jj < 2; jj++) {
                int row = wn * 32 + jj * 16 + b_nloc;
                uint32_t off = ((uint32_t)(row * 128 + kb + b_kb)) ^ ((uint32_t)(row & 7) << 4);
                uint32_t r0, r1, r2, r3;
                LDSM4(r0, r1, r2, r3, sb + off);
                bf[jj * 2][0] = r0; bf[jj * 2][1] = r1;
                bf[jj * 2 + 1][0] = r2; bf[jj * 2 + 1][1] = r3;
            }
#pragma unroll
            for (int i = 0; i < 4; i++)
#pragma unroll
                for (int j = 0; j < 4; j++)
                    MMA_F16(acc[i * 4 + j], af[i][0], af[i][1], af[i][2], af[i][3],
                            bf[j][0], bf[j][1]);
        }
    };

    issue_stage(0);
    if (nch > 1) issue_stage(1);
    else asm volatile("cp.async.commit_group;" ::: "memory");
    for (int c = 0; c < nch; c++) {
        asm volatile("cp.async.wait_group 1;" ::: "memory");
        __syncthreads();
        if (c + 2 < nch) issue_stage(c + 2);
        else asm volatile("cp.async.commit_group;" ::: "memory");
        compute(c % 3);
    }

    int g = lane >> 2, q4 = lane & 3;

    if (MODE == 0 || MODE == 1) {
#pragma unroll
        for (int i = 0; i < 4; i++) {
#pragma unroll
            for (int j = 0; j < 4; j++) {
                int col = n0 + wn * 32 + j * 8 + q4 * 2;
                float b0 = bias[col], b1 = bias[col + 1];
                const float* a4 = acc[i * 4 + j];
#pragma unroll
                for (int half = 0; half < 2; half++) {
                    int mrow = m0 + wm * 64 + i * 16 + g + half * 8;
                    if (mrow >= M) continue;
                    float v0 = a4[half * 2 + 0] + b0;
                    float v1 = a4[half * 2 + 1] + b1;
                    if (MODE == 1) {
                        v0 = fast_gelu(v0);
                        v1 = fast_gelu(v1);
                        *(__half2*)(C16 + (size_t)mrow * Nn + col) = __floats2half2_rn(v0, v1);
                    } else {
                        *(float2*)(C + (size_t)mrow * Nn + col) = make_float2(v0, v1);
                    }
                }
            }
        }
    } else {
        asm volatile("cp.async.wait_group 0;" ::: "memory");
        __syncthreads();
        float* sv = sm;
#pragma unroll
        for (int i = 0; i < 4; i++) {
#pragma unroll
            for (int j = 0; j < 4; j++) {
                int col = wn * 32 + j * 8 + q4 * 2;
                float b0 = bias[col], b1 = bias[col + 1];
                const float* a4 = acc[i * 4 + j];
#pragma unroll
                for (int half = 0; half < 2; half++) {
                    int lr = wm * 64 + i * 16 + g + half * 8;
                    sv[lr * 264 + col]     = a4[half * 2 + 0] + b0;
                    sv[lr * 264 + col + 1] = a4[half * 2 + 1] + b1;
                }
            }
        }
        __syncthreads();
        int lr0 = wid * 8;
#pragma unroll
        for (int rr = 0; rr < 8; rr++) {
            int lr = lr0 + rr;
            size_t m = (size_t)m0 + lr;
            float vals[8];
            if (MODE == 3) {
                int b = (int)(m / Nrows), n = (int)(m % Nrows);
                float ha = d_hasany[b] ? 1.f : 0.f;
#pragma unroll
                for (int jj = 0; jj < 8; jj++) {
                    int e = lane + 32 * jj;
                    vals[jj] = res[(size_t)n * 256 + e] + ha * sv[lr * 264 + e];
                }
            } else {
#pragma unroll
                for (int jj = 0; jj < 8; jj++) {
                    int e = lane + 32 * jj;
                    vals[jj] = sv[lr * 264 + e] + res[m * 256 + e];
                }
            }
            float sum = 0.f;
#pragma unroll
            for (int jj = 0; jj < 8; jj++) sum += vals[jj];
#pragma unroll
            for (int o = 16; o; o >>= 1) sum += __shfl_xor_sync(0xffffffffu, sum, o);
            float mu = sum * (1.f / 256.f);
            float s2 = 0.f;
#pragma unroll
            for (int jj = 0; jj < 8; jj++) { float dd = vals[jj] - mu; s2 += dd * dd; }
#pragma unroll
            for (int o = 16; o; o >>= 1) s2 += __shfl_xor_sync(0xffffffffu, s2, o);
            float rs = rsqrtf(s2 * (1.f / 256.f) + 1e-5f);
#pragma unroll
            for (int jj = 0; jj < 8; jj++) {
                int e = lane + 32 * jj;
                float ov = (vals[jj] - mu) * rs * lg[e] + lb[e];
                C[m * 256 + e] = ov;
                if (MODE == 3) C16[m * 256 + e] = __float2half(ov);
            }
        }
    }
}

// ---------------- k/v projection + segment scan (merged) ------------------------
__global__ void kv_kernel(const float* __restrict__ Hg, const int* __restrict__ idx,
                          const float* __restrict__ ipw, const float* __restrict__ ipb,
                          const int* __restrict__ ba, int P, int B) {
    __shared__ float hrow[Dd];
    int p = blockIdx.x, t = threadIdx.x;
    if (p == 0 && t == 0) {       // segment scan (batch_assignment sorted)
        for (int b = 0; b < B; b++) {
            int s = P, e = 0;
            for (int pp = 0; pp < P; pp++)
                if (ba[pp] == b) { if (pp < s) s = pp; e = pp + 1; }
            if (e > s) { d_segs[2*b] = s; d_segs[2*b+1] = e; d_hasany[b] = 1; }
            else       { d_segs[2*b] = 0; d_segs[2*b+1] = 0; d_hasany[b] = 0; }
        }
    }
    hrow[t] = Hg[(size_t)idx[p] * Dd + t];
    __syncthreads();
    const float4* h4 = (const float4*)hrow;
    const float4* wk = (const float4*)(ipw + (size_t)(Dd + t) * Dd);
    const float4* wv = (const float4*)(ipw + (size_t)(2 * Dd + t) * Dd);
    float ak = ipb[Dd + t], av = ipb[2 * Dd + t];
#pragma unroll 16
    for (int c = 0; c < Dd / 4; c++) {
        float4 hv = h4[c]; float4 a = wk[c]; float4 b = wv[c];
        ak += hv.x*a.x + hv.y*a.y + hv.z*a.z + hv.w*a.w;
        av += hv.x*b.x + hv.y*b.y + hv.z*b.z + hv.w*b.w;
    }
    d_k[p * Dd + t] = ak;
    d_v[p * Dd + t] = av;
}

// ---------------- per-head scores: scale * q_h @ k_h^T -------------------------
__global__ void scores_kernel(int N) {
    int h = blockIdx.y;
    int n0 = blockIdx.x * 64;
    __shared__ float ks[128 * 33];
    __shared__ float qs[64 * 32];
    int tid = threadIdx.x;
    for (int i = tid; i < 128 * 32; i += 256) {
        int p = i >> 5, e = i & 31;
        ks[p * 33 + e] = d_k[p * Dd + h * DHh + e];
    }
    for (int i = tid; i < 64 * 32; i += 256) {
        int r = i >> 5, e = i & 31;
        int n = n0 + r;
        qs[i] = (n < N) ? d_q[(size_t)n * Dd + h * DHh + e] : 0.f;
    }
    __syncthreads();
    int tp = tid & 127, half = tid >> 7;
    float kreg[32];
#pragma unroll
    for (int e = 0; e < 32; e++) kreg[e] = ks[tp * 33 + e];
    const float scale = 0.17677669529663687f;  // 1/sqrt(32)
#pragma unroll 4
    for (int rr = 0; rr < 32; rr++) {
        int r = half * 32 + rr;
        int n = n0 + r;
        if (n >= N) break;
        const float4* q4 = (const float4*)(qs + r * 32);
        float s0 = 0.f, s1 = 0.f, s2 = 0.f, s3 = 0.f;
#pragma unroll
        for (int c = 0; c < 8; c += 4) {
            float4 qa = q4[c],     qb = q4[c + 1];
            float4 qc = q4[c + 2], qd = q4[c + 3];
            s0 += qa.x*kreg[c*4]   + qa.y*kreg[c*4+1] + qa.z*kreg[c*4+2] + qa.w*kreg[c*4+3];
            s1 += qb.x*kreg[c*4+4] + qb.y*kreg[c*4+5] + qb.z*kreg[c*4+6] + qb.w*kreg[c*4+7];
            s2 += qc.x*kreg[c*4+8] + qc.y*kreg[c*4+9] + qc.z*kreg[c*4+10]+ qc.w*kreg[c*4+11];
            s3 += qd.x*kreg[c*4+12]+ qd.y*kreg[c*4+13]+ qd.z*kreg[c*4+14]+ qd.w*kreg[c*4+15];
        }
        d_scores[((size_t)n * Hh + h) * Pmax + tp] = ((s0 + s1) + (s2 + s3)) * scale;
    }
}

// ---------------- segment softmax + ctx accumulation (fp16 out) ----------------
__global__ void attn_kernel(int N) {
    int b = blockIdx.y;
    int h = threadIdx.x >> 5, l = threadIdx.x & 31;
    int s = d_segs[2 * b], e = d_segs[2 * b + 1];
    int L = e - s;
    __shared__ float ws[8][128];
    int nEnd = min(N, (int)(blockIdx.x + 1) * 16);
    for (int n = blockIdx.x * 16; n < nEnd; n++) {
        size_t obase = ((size_t)b * N + n) * Dd + h * DHh;
        if (L <= 0) { d_ctx16[obase + l] = __float2half(0.f); continue; }
        float sc[4]; int cnt = 0;
        float m = -1e30f;
        for (int pl = l; pl < L; pl += 32) {
            float xv = d_scores[((size_t)n * Hh + h) * Pmax + s + pl];
            sc[cnt++] = xv;
            m = fmaxf(m, xv);
        }
#pragma unroll
        for (int o = 16; o; o >>= 1) m = fmaxf(m, __shfl_xor_sync(0xffffffffu, m, o));
        float sum = 0.f; cnt = 0;
        for (int pl = l; pl < L; pl += 32) {
            float w = __expf(sc[cnt++] - m);
            ws[h][pl] = w;
            sum += w;
        }
#pragma unroll
        for (int o = 16; o; o >>= 1) sum += __shfl_xor_sync(0xffffffffu, sum, o);
        float inv = 1.f / sum;
        __syncwarp();
        float acc = 0.f;
        for (int pl = 0; pl < L; pl++)
            acc += ws[h][pl] * d_v[(size_t)(s + pl) * Dd + h * DHh + l];
        d_ctx16[obase + l] = __float2half(acc * inv);
        __syncwarp();
    }
}

// -------------------------------- launch ---------------------------------------
extern "C" void kernel_launch(void* const* d_in, const int* in_sizes, int n_in,
                              void* d_out, int out_size) {
    const float* Hg  = (const float*)d_in[0];
    const int*  pidx = (const int*)d_in[1];
    const int*  ba   = (const int*)d_in[2];
    const float* ipw = (const float*)d_in[4];
    const float* ipb = (const float*)d_in[5];
    const float* opw = (const float*)d_in[6];
    const float* opb = (const float*)d_in[7];
    const float* w1  = (const float*)d_in[8];
    const float* b1  = (const float*)d_in[9];
    const float* w2  = (const float*)d_in[10];
    const float* b2  = (const float*)d_in[11];
    const float* g1  = (const float*)d_in[12];
    const float* be1 = (const float*)d_in[13];
    const float* g2  = (const float*)d_in[14];
    const float* be2 = (const float*)d_in[15];
    float* out = (float*)d_out;

    int N = in_sizes[0] / Dd;          // 6000
    int P = in_sizes[1];               // 128
    int B = out_size / (N * Dd);       // 16
    int M = B * N;                     // 96000

    float *q, *x;
    __half *hg16, *wq16, *wo16, *w116, *w216, *x16, *ctx16, *hidden16;
    cudaGetSymbolAddress((void**)&q,        d_q);
    cudaGetSymbolAddress((void**)&x,        d_x);
    cudaGetSymbolAddress((void**)&hg16,     d_hg16);
    cudaGetSymbolAddress((void**)&wq16,     d_wq16);
    cudaGetSymbolAddress((void**)&wo16,     d_wo16);
    cudaGetSymbolAddress((void**)&w116,     d_w116);
    cudaGetSymbolAddress((void**)&w216,     d_w216);
    cudaGetSymbolAddress((void**)&x16,      d_x16);
    cudaGetSymbolAddress((void**)&ctx16,    d_ctx16);
    cudaGetSymbolAddress((void**)&hidden16, d_hidden16);

    cudaFuncSetAttribute(tgemm<0>, cudaFuncAttributeMaxDynamicSharedMemorySize, SMEM_SZ);
    cudaFuncSetAttribute(tgemm<1>, cudaFuncAttributeMaxDynamicSharedMemorySize, SMEM_SZ);
    cudaFuncSetAttribute(tgemm<3>, cudaFuncAttributeMaxDynamicSharedMemorySize, SMEM_SZ);
    cudaFuncSetAttribute(tgemm<4>, cudaFuncAttributeMaxDynamicSharedMemorySize, SMEM_SZ);

    int tot4 = HG4 + 2 * WQ4 + 2 * W14;
    // 1. single fused fp16 conversion
    f2h_all<<<(tot4 + 255) / 256, 256>>>(Hg, ipw, opw, w1, w2);
    // 2. k/v projections + batch segments
    kv_kernel<<<P, Dd>>>(Hg, pidx, ipw, ipb, ba, P, B);
    // 3. q = H @ Wq^T + bq
    tgemm<0><<<dim3(1, (N + 127) / 128), 512, SMEM_SZ>>>(
        hg16, wq16, ipb, nullptr, q, nullptr, nullptr, nullptr, N, Dd, Dd, N);
    // 4. per-head scores
    scores_kernel<<<dim3((N + 63) / 64, Hh), 256>>>(N);
    // 5. segment softmax + ctx (fp16 out)
    attn_kernel<<<dim3((N + 15) / 16, B), 256>>>(N);
    // 6. x = LN1(H + has_any*(ctx @ Wout^T + bout))  -> fp32 + fp16
    tgemm<3><<<dim3(1, M / 128), 512, SMEM_SZ>>>(
        ctx16, wo16, opb, Hg, x, x16, g1, be1, M, Dd, Dd, N);
    // 7. hidden = fast_gelu(x @ W1^T + b1) -> fp16
    tgemm<1><<<dim3(FF / 256, M / 128), 512, SMEM_SZ>>>(
        x16, w116, b1, nullptr, nullptr, hidden16, nullptr, nullptr, M, FF, Dd, N);
    // 8. out = LN2(x + hidden @ W2^T + b2)
    tgemm<4><<<dim3(1, M / 128), 512, SMEM_SZ>>>(
        hidden16, w216, b2, x, out, nullptr, g2, be2, M, Dd, FF, N);
}